// round 1
// baseline (speedup 1.0000x reference)
#include <cuda_runtime.h>

// Problem constants (fixed shapes from reference setup_inputs)
#define Bb 8
#define Tt 2048
#define Mm 1024
#define Ff 2048
#define Ee 8
#define Ss 16384          // B*T
#define CAP 2048          // capacity = ceil(S/E)
#define ECAP 16384        // E*CAP
#define DROPPED 0x7FFFFFFF

// Scratch (device globals; no allocations allowed)
__device__ float g_dk[(size_t)ECAP * Mm];   // dispatched xk   (E,cap,m)
__device__ float g_dr[(size_t)ECAP * Mm];   // dispatched xr   (E,cap,m)
__device__ float g_h [(size_t)ECAP * Ff];   // relu^2(dk@Wk)   (E,cap,f)
__device__ float g_kv[(size_t)ECAP * Mm];   // h@Wv            (E,cap,m)
__device__ float g_r [(size_t)ECAP * Mm];   // sigmoid(dr@Wr)  (E,cap,m)
__device__ int   g_slot2tok[ECAP];
__device__ int   g_tok2slot[Ss];

// ---------------------------------------------------------------------------
// Routing: exact order-preserving per-expert cumulative positions.
// Single block, 256 threads, 64 tokens/thread, two-pass scan.
// ---------------------------------------------------------------------------
__global__ void route_kernel(const int* __restrict__ tok) {
    __shared__ int cnt[256][8];
    const int t = threadIdx.x;

    // init slot->token map
    for (int i = t; i < ECAP; i += 256) g_slot2tok[i] = -1;

    const int base = t * 64;
    int c[8] = {0,0,0,0,0,0,0,0};
    #pragma unroll 4
    for (int i = 0; i < 64; ++i) {
        int e = (tok[base + i] * 5099) & 7;   // HASH_PRIME % E (E=8)
        c[e]++;
    }
    #pragma unroll
    for (int e = 0; e < 8; ++e) cnt[t][e] = c[e];
    __syncthreads();

    // exclusive scan of each expert column (8 threads, one column each)
    if (t < 8) {
        int run = 0;
        for (int j = 0; j < 256; ++j) {
            int v = cnt[j][t];
            cnt[j][t] = run;
            run += v;
        }
    }
    __syncthreads();

    int run[8];
    #pragma unroll
    for (int e = 0; e < 8; ++e) run[e] = cnt[t][e];

    for (int i = 0; i < 64; ++i) {
        int s = base + i;
        int e = (tok[s] * 5099) & 7;
        int pos = run[e]++;
        if (pos < CAP) {
            int slot = e * CAP + pos;
            g_tok2slot[s] = slot;
            g_slot2tok[slot] = s;
        } else {
            g_tok2slot[s] = DROPPED;
        }
    }
}

// ---------------------------------------------------------------------------
// Dispatch: build dk,dr buffers. One block per slot, float4 per thread.
// ---------------------------------------------------------------------------
__global__ void dispatch_kernel(const float* __restrict__ x,
                                const float* __restrict__ shift,
                                const float* __restrict__ maak,
                                const float* __restrict__ maar) {
    const int slot = blockIdx.x;
    const int j = threadIdx.x * 4;
    const size_t o = (size_t)slot * Mm + j;
    const int tokidx = g_slot2tok[slot];
    if (tokidx < 0) {
        float4 z = make_float4(0.f, 0.f, 0.f, 0.f);
        *(float4*)&g_dk[o] = z;
        *(float4*)&g_dr[o] = z;
        return;
    }
    const int b = tokidx / Tt;
    const int t = tokidx % Tt;
    float4 xv = *(const float4*)&x[(size_t)tokidx * Mm + j];
    float4 xp;
    if (t == 0) xp = *(const float4*)&shift[(size_t)b * Mm + j];
    else        xp = *(const float4*)&x[(size_t)(tokidx - 1) * Mm + j];
    float4 mk = *(const float4*)&maak[j];
    float4 mr = *(const float4*)&maar[j];
    float4 dx = make_float4(xp.x - xv.x, xp.y - xv.y, xp.z - xv.z, xp.w - xv.w);
    float4 dk = make_float4(fmaf(dx.x, mk.x, xv.x), fmaf(dx.y, mk.y, xv.y),
                            fmaf(dx.z, mk.z, xv.z), fmaf(dx.w, mk.w, xv.w));
    float4 dr = make_float4(fmaf(dx.x, mr.x, xv.x), fmaf(dx.y, mr.y, xv.y),
                            fmaf(dx.z, mr.z, xv.z), fmaf(dx.w, mr.w, xv.w));
    *(float4*)&g_dk[o] = dk;
    *(float4*)&g_dr[o] = dr;
}

// ---------------------------------------------------------------------------
// SGEMM: C[M,N] = A[M,K] @ B[K,N], per-expert via blockIdx.z.
// 128x128 block tile, BK=8, 8x8 microtile, 256 threads, double-buffered smem.
// EPI: 0 = relu^2, 1 = identity, 2 = sigmoid.
// ---------------------------------------------------------------------------
template<int EPI>
__global__ void __launch_bounds__(256, 2)
gemm_kernel(const float* __restrict__ Ag, const float* __restrict__ Bg,
            float* __restrict__ Cg, int M, int N, int K) {
    const long e = blockIdx.z;
    const float* A  = Ag + e * (long)M * K;
    const float* Bp = Bg + e * (long)K * N;
    float*       C  = Cg + e * (long)M * N;

    const int bm = blockIdx.y * 128;
    const int bn = blockIdx.x * 128;
    const int tid = threadIdx.x;

    __shared__ float As[2][8][128];
    __shared__ float Bs[2][8][128];

    const int arow = tid >> 1;
    const int acol = (tid & 1) * 4;
    const int brow = tid >> 5;
    const int bcol = (tid & 31) * 4;

    const float* Aptr = A + (long)(bm + arow) * K + acol;
    const float* Bptr = Bp + (long)brow * N + bn + bcol;

    // first tile
    {
        float4 a4 = *(const float4*)Aptr;
        float4 b4 = *(const float4*)Bptr;
        As[0][acol + 0][arow] = a4.x;
        As[0][acol + 1][arow] = a4.y;
        As[0][acol + 2][arow] = a4.z;
        As[0][acol + 3][arow] = a4.w;
        *(float4*)&Bs[0][brow][bcol] = b4;
    }
    __syncthreads();

    const int tx = tid & 15;
    const int ty = tid >> 4;
    float acc[8][8];
    #pragma unroll
    for (int i = 0; i < 8; ++i)
        #pragma unroll
        for (int j = 0; j < 8; ++j) acc[i][j] = 0.f;

    const int KT = K >> 3;
    int buf = 0;
    for (int kt = 0; kt < KT; ++kt) {
        float4 na, nb;
        const bool more = (kt + 1 < KT);
        if (more) {
            na = *(const float4*)(Aptr + (kt + 1) * 8);
            nb = *(const float4*)(Bptr + (long)(kt + 1) * 8 * N);
        }
        #pragma unroll
        for (int k = 0; k < 8; ++k) {
            float ra[8], rb[8];
            *(float4*)&ra[0] = *(const float4*)&As[buf][k][ty * 8];
            *(float4*)&ra[4] = *(const float4*)&As[buf][k][ty * 8 + 4];
            *(float4*)&rb[0] = *(const float4*)&Bs[buf][k][tx * 8];
            *(float4*)&rb[4] = *(const float4*)&Bs[buf][k][tx * 8 + 4];
            #pragma unroll
            for (int i = 0; i < 8; ++i)
                #pragma unroll
                for (int j = 0; j < 8; ++j)
                    acc[i][j] = fmaf(ra[i], rb[j], acc[i][j]);
        }
        if (more) {
            int nbuf = buf ^ 1;
            As[nbuf][acol + 0][arow] = na.x;
            As[nbuf][acol + 1][arow] = na.y;
            As[nbuf][acol + 2][arow] = na.z;
            As[nbuf][acol + 3][arow] = na.w;
            *(float4*)&Bs[nbuf][brow][bcol] = nb;
            __syncthreads();
            buf = nbuf;
        }
    }

    // epilogue
    #pragma unroll
    for (int i = 0; i < 8; ++i) {
        long row = bm + ty * 8 + i;
        float* Crow = C + row * (long)N + bn + tx * 8;
        float v[8];
        #pragma unroll
        for (int j = 0; j < 8; ++j) {
            float val = acc[i][j];
            if (EPI == 0) {            // relu then square
                val = val > 0.f ? val * val : 0.f;
            } else if (EPI == 2) {     // sigmoid
                val = 1.f / (1.f + expf(-val));
            }
            v[j] = val;
        }
        *(float4*)&Crow[0] = make_float4(v[0], v[1], v[2], v[3]);
        *(float4*)&Crow[4] = make_float4(v[4], v[5], v[6], v[7]);
    }
}

// ---------------------------------------------------------------------------
// Combine: out[token] = r[slot] * kv[slot], 0 for dropped tokens.
// ---------------------------------------------------------------------------
__global__ void combine_kernel(float* __restrict__ out) {
    const int s = blockIdx.x;
    const int j = threadIdx.x * 4;
    const size_t oo = (size_t)s * Mm + j;
    const int slot = g_tok2slot[s];
    float4 o = make_float4(0.f, 0.f, 0.f, 0.f);
    if (slot < ECAP) {
        const size_t so = (size_t)slot * Mm + j;
        float4 rv = *(const float4*)&g_r[so];
        float4 kv = *(const float4*)&g_kv[so];
        o = make_float4(rv.x * kv.x, rv.y * kv.y, rv.z * kv.z, rv.w * kv.w);
    }
    *(float4*)&out[oo] = o;
}

// new_shift_state = x[:, -1]
__global__ void shift_kernel(const float* __restrict__ x, float* __restrict__ out) {
    const int b = blockIdx.x;
    const int j = threadIdx.x * 4;
    *(float4*)&out[(size_t)Ss * Mm + (size_t)b * Mm + j] =
        *(const float4*)&x[((size_t)b * Tt + (Tt - 1)) * Mm + j];
}

// ---------------------------------------------------------------------------
extern "C" void kernel_launch(void* const* d_in, const int* in_sizes, int n_in,
                              void* d_out, int out_size) {
    const float* x     = (const float*)d_in[0];
    const int*   tok   = (const int*)  d_in[1];
    const float* shift = (const float*)d_in[2];
    const float* maak  = (const float*)d_in[3];
    const float* maar  = (const float*)d_in[4];
    const float* Wk    = (const float*)d_in[5];
    const float* Wv    = (const float*)d_in[6];
    const float* Wr    = (const float*)d_in[7];
    float* out = (float*)d_out;

    float *dk, *dr, *h, *kv, *r;
    cudaGetSymbolAddress((void**)&dk, g_dk);
    cudaGetSymbolAddress((void**)&dr, g_dr);
    cudaGetSymbolAddress((void**)&h,  g_h);
    cudaGetSymbolAddress((void**)&kv, g_kv);
    cudaGetSymbolAddress((void**)&r,  g_r);

    route_kernel<<<1, 256>>>(tok);
    dispatch_kernel<<<ECAP, 256>>>(x, shift, maak, maar);

    // h = relu^2(dk @ Wk)    (per expert: 2048x2048x1024)
    dim3 g1(Ff / 128, CAP / 128, Ee);
    gemm_kernel<0><<<g1, 256>>>(dk, Wk, h, CAP, Ff, Mm);

    // kv = h @ Wv            (per expert: 2048x1024x2048)
    dim3 g2(Mm / 128, CAP / 128, Ee);
    gemm_kernel<1><<<g2, 256>>>(h, Wv, kv, CAP, Mm, Ff);

    // r = sigmoid(dr @ Wr)   (per expert: 2048x1024x1024)
    gemm_kernel<2><<<g2, 256>>>(dr, Wr, r, CAP, Mm, Mm);

    combine_kernel<<<Ss, 256>>>(out);

    if ((size_t)out_size >= (size_t)Ss * Mm + (size_t)Bb * Mm)
        shift_kernel<<<Bb, 256>>>(x, out);
}

// round 3
// speedup vs baseline: 2.7446x; 2.7446x over previous
#include <cuda_runtime.h>
#include <cuda_bf16.h>
#include <stdint.h>

// ---------------------------------------------------------------------------
// Problem constants
// ---------------------------------------------------------------------------
#define Bb 8
#define Tt 2048
#define Mm 1024
#define Ff 2048
#define Ee 8
#define Ss 16384
#define CAP 2048
#define ECAP 16384
#define DROPPED 0x7FFFFFFF

// Split layouts (bf16):  A' = [Ah | Ah | Al],  B' = [Bh | Bl | Bh]
__device__ __align__(128) __nv_bfloat16 g_dk_b[(size_t)ECAP * 3072];
__device__ __align__(128) __nv_bfloat16 g_dr_b[(size_t)ECAP * 3072];
__device__ __align__(128) __nv_bfloat16 g_h_b [(size_t)ECAP * 6144];
__device__ __align__(128) __nv_bfloat16 g_Wk_b[(size_t)Ee * 2048 * 3072];
__device__ __align__(128) __nv_bfloat16 g_Wv_b[(size_t)Ee * 1024 * 6144];
__device__ __align__(128) __nv_bfloat16 g_Wr_b[(size_t)Ee * 1024 * 3072];
__device__ float g_kv[(size_t)ECAP * Mm];
__device__ float g_r [(size_t)ECAP * Mm];
__device__ int   g_slot2tok[ECAP];
__device__ int   g_tok2slot[Ss];

// ---------------------------------------------------------------------------
// PTX helpers (base sm_103 target only: cp.async / ldmatrix / mma.sync)
// ---------------------------------------------------------------------------
__device__ __forceinline__ uint32_t smem_u32(const void* p) {
    uint32_t a;
    asm("{ .reg .u64 t; cvta.to.shared.u64 t, %1; cvt.u32.u64 %0, t; }" : "=r"(a) : "l"(p));
    return a;
}
__device__ __forceinline__ void cp16(uint32_t s, const void* g) {
    asm volatile("cp.async.cg.shared.global [%0], [%1], 16;" :: "r"(s), "l"(g) : "memory");
}
#define CP_COMMIT() asm volatile("cp.async.commit_group;" ::: "memory")
#define CP_WAIT2()  asm volatile("cp.async.wait_group 2;" ::: "memory")

#define LDSM_X4(r, a) \
    asm volatile("ldmatrix.sync.aligned.m8n8.x4.shared.b16 {%0,%1,%2,%3}, [%4];" \
        : "=r"((r)[0]), "=r"((r)[1]), "=r"((r)[2]), "=r"((r)[3]) : "r"(a))

__device__ __forceinline__ void mma16816(float* c, const uint32_t* a,
                                         uint32_t b0, uint32_t b1) {
    asm volatile(
        "mma.sync.aligned.m16n8k16.row.col.f32.bf16.bf16.f32 "
        "{%0,%1,%2,%3}, {%4,%5,%6,%7}, {%8,%9}, {%0,%1,%2,%3};"
        : "+f"(c[0]), "+f"(c[1]), "+f"(c[2]), "+f"(c[3])
        : "r"(a[0]), "r"(a[1]), "r"(a[2]), "r"(a[3]), "r"(b0), "r"(b1));
}

// ---------------------------------------------------------------------------
// Routing: exact order-preserving per-expert positions
// ---------------------------------------------------------------------------
__global__ void route_kernel(const int* __restrict__ tok) {
    __shared__ int cnt[256][8];
    const int t = threadIdx.x;
    for (int i = t; i < ECAP; i += 256) g_slot2tok[i] = -1;
    const int base = t * 64;
    int c[8] = {0,0,0,0,0,0,0,0};
    for (int i = 0; i < 64; ++i) { int e = (tok[base + i] * 5099) & 7; c[e]++; }
    #pragma unroll
    for (int e = 0; e < 8; ++e) cnt[t][e] = c[e];
    __syncthreads();
    if (t < 8) {
        int run = 0;
        for (int j = 0; j < 256; ++j) { int v = cnt[j][t]; cnt[j][t] = run; run += v; }
    }
    __syncthreads();
    int run[8];
    #pragma unroll
    for (int e = 0; e < 8; ++e) run[e] = cnt[t][e];
    for (int i = 0; i < 64; ++i) {
        int s = base + i;
        int e = (tok[s] * 5099) & 7;
        int pos = run[e]++;
        if (pos < CAP) { int slot = e * CAP + pos; g_tok2slot[s] = slot; g_slot2tok[slot] = s; }
        else g_tok2slot[s] = DROPPED;
    }
}

// ---------------------------------------------------------------------------
// Dispatch: token-shift mix, write bf16 split [Ah|Ah|Al]
// ---------------------------------------------------------------------------
__device__ __forceinline__ void split_store4(__nv_bfloat16* row, int j, float4 v, int K) {
    __nv_bfloat16 h0 = __float2bfloat16(v.x), h1 = __float2bfloat16(v.y);
    __nv_bfloat16 h2 = __float2bfloat16(v.z), h3 = __float2bfloat16(v.w);
    __nv_bfloat16 l0 = __float2bfloat16(v.x - __bfloat162float(h0));
    __nv_bfloat16 l1 = __float2bfloat16(v.y - __bfloat162float(h1));
    __nv_bfloat16 l2 = __float2bfloat16(v.z - __bfloat162float(h2));
    __nv_bfloat16 l3 = __float2bfloat16(v.w - __bfloat162float(h3));
    *(__nv_bfloat162*)(row + j)             = __halves2bfloat162(h0, h1);
    *(__nv_bfloat162*)(row + j + 2)         = __halves2bfloat162(h2, h3);
    *(__nv_bfloat162*)(row + K + j)         = __halves2bfloat162(h0, h1);
    *(__nv_bfloat162*)(row + K + j + 2)     = __halves2bfloat162(h2, h3);
    *(__nv_bfloat162*)(row + 2 * K + j)     = __halves2bfloat162(l0, l1);
    *(__nv_bfloat162*)(row + 2 * K + j + 2) = __halves2bfloat162(l2, l3);
}

__global__ void dispatch_kernel(const float* __restrict__ x,
                                const float* __restrict__ shift,
                                const float* __restrict__ maak,
                                const float* __restrict__ maar) {
    const int slot = blockIdx.x;
    const int j = threadIdx.x * 4;
    __nv_bfloat16* rk = g_dk_b + (size_t)slot * 3072;
    __nv_bfloat16* rr = g_dr_b + (size_t)slot * 3072;
    const int tokidx = g_slot2tok[slot];
    if (tokidx < 0) {
        float4 z = make_float4(0.f, 0.f, 0.f, 0.f);
        split_store4(rk, j, z, 1024);
        split_store4(rr, j, z, 1024);
        return;
    }
    const int b = tokidx / Tt;
    const int t = tokidx % Tt;
    float4 xv = *(const float4*)&x[(size_t)tokidx * Mm + j];
    float4 xp;
    if (t == 0) xp = *(const float4*)&shift[(size_t)b * Mm + j];
    else        xp = *(const float4*)&x[(size_t)(tokidx - 1) * Mm + j];
    float4 mk = *(const float4*)&maak[j];
    float4 mr = *(const float4*)&maar[j];
    float4 dx = make_float4(xp.x - xv.x, xp.y - xv.y, xp.z - xv.z, xp.w - xv.w);
    float4 dk = make_float4(fmaf(dx.x, mk.x, xv.x), fmaf(dx.y, mk.y, xv.y),
                            fmaf(dx.z, mk.z, xv.z), fmaf(dx.w, mk.w, xv.w));
    float4 dr = make_float4(fmaf(dx.x, mr.x, xv.x), fmaf(dx.y, mr.y, xv.y),
                            fmaf(dx.z, mr.z, xv.z), fmaf(dx.w, mr.w, xv.w));
    split_store4(rk, j, dk, 1024);
    split_store4(rr, j, dr, 1024);
}

// ---------------------------------------------------------------------------
// Weight transpose+split:  W [E][K][N] fp32  ->  W' [E][N][3K] bf16 [Bh|Bl|Bh]
// ---------------------------------------------------------------------------
__global__ void wconv_kernel(const float* __restrict__ W, __nv_bfloat16* __restrict__ out,
                             int K, int N) {
    __shared__ float tile[32][33];
    const int e = blockIdx.z;
    const float* Wp = W + (size_t)e * K * N;
    __nv_bfloat16* op = out + (size_t)e * N * 3 * K;
    const int k0 = blockIdx.y * 32, n0 = blockIdx.x * 32;
    const int tx = threadIdx.x, ty = threadIdx.y;
    #pragma unroll
    for (int i = 0; i < 32; i += 8)
        tile[ty + i][tx] = Wp[(size_t)(k0 + ty + i) * N + n0 + tx];
    __syncthreads();
    #pragma unroll
    for (int i = 0; i < 32; i += 8) {
        float v = tile[tx][ty + i];
        __nv_bfloat16 hi = __float2bfloat16(v);
        __nv_bfloat16 lo = __float2bfloat16(v - __bfloat162float(hi));
        size_t base = (size_t)(n0 + ty + i) * 3 * K + k0 + tx;
        op[base]         = hi;
        op[base + K]     = lo;
        op[base + 2 * K] = hi;
    }
}

// ---------------------------------------------------------------------------
// HMMA GEMM: per expert C[2048 x N] = A'[2048 x Kp] @ B'[N x Kp]^T
// 128x128 tile, 32-k step, 4-stage cp.async, 8 warps (4M x 2N).
// EPI: 0 = relu^2 + bf16 split (into next A'), 1 = copy f32, 2 = sigmoid f32
// ---------------------------------------------------------------------------
constexpr int STAGE_B  = 16384;          // A 8KB + B 8KB
constexpr int GEMM_SMEM = 4 * STAGE_B;   // 64 KB

template<int EPI>
__global__ void __launch_bounds__(256, 2)
gemm_mma(const __nv_bfloat16* __restrict__ Ag, const __nv_bfloat16* __restrict__ Bg,
         float* __restrict__ Cf, __nv_bfloat16* __restrict__ Cb,
         int Kp, int N) {
    extern __shared__ __align__(1024) char smem[];
    const uint32_t sb = smem_u32(smem);
    const int tid = threadIdx.x;
    const int lane = tid & 31, warp = tid >> 5;
    const int wm = warp & 3, wn = warp >> 2;
    const int e = blockIdx.z;
    const int bm = blockIdx.y * 128, bn = blockIdx.x * 128;

    const __nv_bfloat16* A = Ag + ((size_t)e * 2048 + bm) * Kp;
    const __nv_bfloat16* B = Bg + ((size_t)e * N + bn) * Kp;

    // cp.async loader: 128 rows x 64B per tile, swizzle unit ^= (row>>1)&3
    const int r0u = tid >> 2,        c0u = tid & 3;
    const int r1u = (tid + 256) >> 2, c1u = tid & 3;
    const uint32_t dA0 = (uint32_t)(r0u * 64 + ((c0u ^ ((r0u >> 1) & 3)) << 4));
    const uint32_t dA1 = (uint32_t)(r1u * 64 + ((c1u ^ ((r1u >> 1) & 3)) << 4));

    #define LOAD_STAGE(st, kt) do {                                              \
        uint32_t _b = sb + (st) * STAGE_B;                                        \
        cp16(_b + dA0,        A + (size_t)r0u * Kp + (kt) * 32 + c0u * 8);        \
        cp16(_b + dA1,        A + (size_t)r1u * Kp + (kt) * 32 + c1u * 8);        \
        cp16(_b + 8192 + dA0, B + (size_t)r0u * Kp + (kt) * 32 + c0u * 8);        \
        cp16(_b + 8192 + dA1, B + (size_t)r1u * Kp + (kt) * 32 + c1u * 8);        \
    } while (0)

    // ldmatrix per-lane offsets
    const int rowA = wm * 32 + (lane & 15);
    const uint32_t aOff = (uint32_t)(rowA * 64 +
                          (((lane >> 4) ^ ((rowA >> 1) & 3)) << 4));
    const int rowB = wn * 64 + (lane & 7) + ((lane >> 4) << 3);
    const uint32_t bOff = (uint32_t)(rowB * 64 +
                          ((((lane >> 3) & 1) ^ ((rowB >> 1) & 3)) << 4));

    float acc[2][8][4];
    #pragma unroll
    for (int i = 0; i < 2; ++i)
        #pragma unroll
        for (int j = 0; j < 8; ++j)
            #pragma unroll
            for (int k = 0; k < 4; ++k) acc[i][j][k] = 0.f;

    const int KT = Kp / 32;
    LOAD_STAGE(0, 0); CP_COMMIT();
    LOAD_STAGE(1, 1); CP_COMMIT();
    LOAD_STAGE(2, 2); CP_COMMIT();

    for (int kt = 0; kt < KT; ++kt) {
        CP_WAIT2();
        __syncthreads();
        if (kt + 3 < KT) LOAD_STAGE((kt + 3) & 3, kt + 3);
        CP_COMMIT();

        const uint32_t stb = sb + (kt & 3) * STAGE_B;
        #pragma unroll
        for (int ks = 0; ks < 2; ++ks) {
            const uint32_t kx = ks * 32;
            uint32_t a[2][4];
            #pragma unroll
            for (int mi = 0; mi < 2; ++mi)
                LDSM_X4(a[mi], (stb + aOff + mi * 1024) ^ kx);
            uint32_t b[4][4];
            #pragma unroll
            for (int nf2 = 0; nf2 < 4; ++nf2)
                LDSM_X4(b[nf2], (stb + 8192 + bOff + nf2 * 1024) ^ kx);
            #pragma unroll
            for (int mi = 0; mi < 2; ++mi)
                #pragma unroll
                for (int nf2 = 0; nf2 < 4; ++nf2) {
                    mma16816(acc[mi][nf2 * 2 + 0], a[mi], b[nf2][0], b[nf2][1]);
                    mma16816(acc[mi][nf2 * 2 + 1], a[mi], b[nf2][2], b[nf2][3]);
                }
        }
    }

    // Epilogue
    #pragma unroll
    for (int mi = 0; mi < 2; ++mi) {
        #pragma unroll
        for (int nf = 0; nf < 8; ++nf) {
            const float* c = acc[mi][nf];
            const int col = bn + wn * 64 + nf * 8 + (lane & 3) * 2;
            const int row0 = bm + wm * 32 + mi * 16 + (lane >> 2);
            #pragma unroll
            for (int h = 0; h < 2; ++h) {
                const int row = row0 + h * 8;
                float v0 = c[h * 2 + 0], v1 = c[h * 2 + 1];
                if (EPI == 0) {
                    v0 = v0 > 0.f ? v0 * v0 : 0.f;
                    v1 = v1 > 0.f ? v1 * v1 : 0.f;
                    __nv_bfloat16 h0 = __float2bfloat16(v0);
                    __nv_bfloat16 h1 = __float2bfloat16(v1);
                    __nv_bfloat16 l0 = __float2bfloat16(v0 - __bfloat162float(h0));
                    __nv_bfloat16 l1 = __float2bfloat16(v1 - __bfloat162float(h1));
                    __nv_bfloat16* p = Cb + ((size_t)e * 2048 + row) * (size_t)(3 * N) + col;
                    *(__nv_bfloat162*)p           = __halves2bfloat162(h0, h1);
                    *(__nv_bfloat162*)(p + N)     = __halves2bfloat162(h0, h1);
                    *(__nv_bfloat162*)(p + 2 * N) = __halves2bfloat162(l0, l1);
                } else {
                    if (EPI == 2) {
                        v0 = 1.f / (1.f + __expf(-v0));
                        v1 = 1.f / (1.f + __expf(-v1));
                    }
                    float* p = Cf + ((size_t)e * 2048 + row) * (size_t)N + col;
                    *(float2*)p = make_float2(v0, v1);
                }
            }
        }
    }
    #undef LOAD_STAGE
}

// ---------------------------------------------------------------------------
// Combine + shift
// ---------------------------------------------------------------------------
__global__ void combine_kernel(float* __restrict__ out) {
    const int s = blockIdx.x;
    const int j = threadIdx.x * 4;
    const size_t oo = (size_t)s * Mm + j;
    const int slot = g_tok2slot[s];
    float4 o = make_float4(0.f, 0.f, 0.f, 0.f);
    if (slot < ECAP) {
        const size_t so = (size_t)slot * Mm + j;
        float4 rv = *(const float4*)&g_r[so];
        float4 kv = *(const float4*)&g_kv[so];
        o = make_float4(rv.x * kv.x, rv.y * kv.y, rv.z * kv.z, rv.w * kv.w);
    }
    *(float4*)&out[oo] = o;
}
__global__ void shift_kernel(const float* __restrict__ x, float* __restrict__ out) {
    const int b = blockIdx.x;
    const int j = threadIdx.x * 4;
    *(float4*)&out[(size_t)Ss * Mm + (size_t)b * Mm + j] =
        *(const float4*)&x[((size_t)b * Tt + (Tt - 1)) * Mm + j];
}

// ---------------------------------------------------------------------------
// Host
// ---------------------------------------------------------------------------
extern "C" void kernel_launch(void* const* d_in, const int* in_sizes, int n_in,
                              void* d_out, int out_size) {
    const float* x     = (const float*)d_in[0];
    const int*   tok   = (const int*)  d_in[1];
    const float* shift = (const float*)d_in[2];
    const float* maak  = (const float*)d_in[3];
    const float* maar  = (const float*)d_in[4];
    const float* Wk    = (const float*)d_in[5];
    const float* Wv    = (const float*)d_in[6];
    const float* Wr    = (const float*)d_in[7];
    float* out = (float*)d_out;

    void *dkb, *drb, *hb, *wkb, *wvb, *wrb, *kvp, *rp;
    cudaGetSymbolAddress(&dkb, g_dk_b);
    cudaGetSymbolAddress(&drb, g_dr_b);
    cudaGetSymbolAddress(&hb,  g_h_b);
    cudaGetSymbolAddress(&wkb, g_Wk_b);
    cudaGetSymbolAddress(&wvb, g_Wv_b);
    cudaGetSymbolAddress(&wrb, g_Wr_b);
    cudaGetSymbolAddress(&kvp, g_kv);
    cudaGetSymbolAddress(&rp,  g_r);

    cudaFuncSetAttribute(gemm_mma<0>, cudaFuncAttributeMaxDynamicSharedMemorySize, GEMM_SMEM);
    cudaFuncSetAttribute(gemm_mma<1>, cudaFuncAttributeMaxDynamicSharedMemorySize, GEMM_SMEM);
    cudaFuncSetAttribute(gemm_mma<2>, cudaFuncAttributeMaxDynamicSharedMemorySize, GEMM_SMEM);

    route_kernel<<<1, 256>>>(tok);
    dispatch_kernel<<<ECAP, 256>>>(x, shift, maak, maar);
    wconv_kernel<<<dim3(64, 32, 8), dim3(32, 8)>>>(Wk, (__nv_bfloat16*)wkb, 1024, 2048);
    wconv_kernel<<<dim3(32, 64, 8), dim3(32, 8)>>>(Wv, (__nv_bfloat16*)wvb, 2048, 1024);
    wconv_kernel<<<dim3(32, 32, 8), dim3(32, 8)>>>(Wr, (__nv_bfloat16*)wrb, 1024, 1024);

    // h' = split(relu^2(dk' @ Wk'^T))   per expert 2048x2048, K'=3072
    gemm_mma<0><<<dim3(16, 16, 8), 256, GEMM_SMEM>>>(
        (const __nv_bfloat16*)dkb, (const __nv_bfloat16*)wkb,
        nullptr, (__nv_bfloat16*)hb, 3072, 2048);
    // kv = h' @ Wv'^T                   per expert 2048x1024, K'=6144
    gemm_mma<1><<<dim3(8, 16, 8), 256, GEMM_SMEM>>>(
        (const __nv_bfloat16*)hb, (const __nv_bfloat16*)wvb,
        (float*)kvp, nullptr, 6144, 1024);
    // r = sigmoid(dr' @ Wr'^T)          per expert 2048x1024, K'=3072
    gemm_mma<2><<<dim3(8, 16, 8), 256, GEMM_SMEM>>>(
        (const __nv_bfloat16*)drb, (const __nv_bfloat16*)wrb,
        (float*)rp, nullptr, 3072, 1024);

    combine_kernel<<<Ss, 256>>>(out);
    if ((size_t)out_size >= (size_t)Ss * Mm + (size_t)Bb * Mm)
        shift_kernel<<<Bb, 256>>>(x, out);
}

// round 4
// speedup vs baseline: 3.4784x; 1.2674x over previous
#include <cuda_runtime.h>
#include <cuda_bf16.h>
#include <cuda_fp16.h>
#include <stdint.h>

// ---------------------------------------------------------------------------
// Problem constants
// ---------------------------------------------------------------------------
#define Bb 8
#define Tt 2048
#define Mm 1024
#define Ff 2048
#define Ee 8
#define Ss 16384
#define CAP 2048
#define ECAP 16384
#define DROPPED 0x7FFFFFFF

// Dedup split storage:
//  dk  : bf16 [ECAP][2048]   = [Ah | Al]           (GEMM1 A, 3-term via LUT)
//  dr  : fp16 [ECAP][2048]   = [Ah | Al]           (GEMM3 A, 2-term)
//  h   : fp16 [ECAP][4096]   = [Hh | Hl]           (GEMM2 A, 2-term)
//  Wk' : bf16 [E][2048][2048] = [Bh | Bl] (N-major) (GEMM1 B)
//  Wv' : fp16 [E][1024][2048]                       (GEMM2 B, hi only)
//  Wr' : fp16 [E][1024][1024]                       (GEMM3 B, hi only)
__device__ __align__(128) __nv_bfloat16 g_dk_b[(size_t)ECAP * 2048];
__device__ __align__(128) __half        g_dr_h[(size_t)ECAP * 2048];
__device__ __align__(128) __half        g_h_h [(size_t)ECAP * 4096];
__device__ __align__(128) __nv_bfloat16 g_Wk_b[(size_t)Ee * 2048 * 2048];
__device__ __align__(128) __half        g_Wv_h[(size_t)Ee * 1024 * 2048];
__device__ __align__(128) __half        g_Wr_h[(size_t)Ee * 1024 * 1024];
__device__ float g_kv[(size_t)ECAP * Mm];
__device__ float g_r [(size_t)ECAP * Mm];
__device__ int   g_slot2tok[ECAP];
__device__ int   g_tok2slot[Ss];

// ---------------------------------------------------------------------------
// PTX helpers (base sm_103 target: cp.async / ldmatrix / mma.sync)
// ---------------------------------------------------------------------------
__device__ __forceinline__ uint32_t smem_u32(const void* p) {
    uint32_t a;
    asm("{ .reg .u64 t; cvta.to.shared.u64 t, %1; cvt.u32.u64 %0, t; }" : "=r"(a) : "l"(p));
    return a;
}
__device__ __forceinline__ void cp16(uint32_t s, const void* g) {
    asm volatile("cp.async.cg.shared.global [%0], [%1], 16;" :: "r"(s), "l"(g) : "memory");
}
#define CP_COMMIT() asm volatile("cp.async.commit_group;" ::: "memory")
#define CP_WAIT2()  asm volatile("cp.async.wait_group 2;" ::: "memory")

#define LDSM_X4(r, a) \
    asm volatile("ldmatrix.sync.aligned.m8n8.x4.shared.b16 {%0,%1,%2,%3}, [%4];" \
        : "=r"((r)[0]), "=r"((r)[1]), "=r"((r)[2]), "=r"((r)[3]) : "r"(a))

__device__ __forceinline__ void mma_bf16(float* c, const uint32_t* a,
                                         uint32_t b0, uint32_t b1) {
    asm volatile(
        "mma.sync.aligned.m16n8k16.row.col.f32.bf16.bf16.f32 "
        "{%0,%1,%2,%3}, {%4,%5,%6,%7}, {%8,%9}, {%0,%1,%2,%3};"
        : "+f"(c[0]), "+f"(c[1]), "+f"(c[2]), "+f"(c[3])
        : "r"(a[0]), "r"(a[1]), "r"(a[2]), "r"(a[3]), "r"(b0), "r"(b1));
}
__device__ __forceinline__ void mma_fp16(float* c, const uint32_t* a,
                                         uint32_t b0, uint32_t b1) {
    asm volatile(
        "mma.sync.aligned.m16n8k16.row.col.f32.f16.f16.f32 "
        "{%0,%1,%2,%3}, {%4,%5,%6,%7}, {%8,%9}, {%0,%1,%2,%3};"
        : "+f"(c[0]), "+f"(c[1]), "+f"(c[2]), "+f"(c[3])
        : "r"(a[0]), "r"(a[1]), "r"(a[2]), "r"(a[3]), "r"(b0), "r"(b1));
}

// ---------------------------------------------------------------------------
// Routing: exact order-preserving per-expert positions
// ---------------------------------------------------------------------------
__global__ void route_kernel(const int* __restrict__ tok) {
    __shared__ int cnt[256][8];
    const int t = threadIdx.x;
    for (int i = t; i < ECAP; i += 256) g_slot2tok[i] = -1;
    const int base = t * 64;
    int c[8] = {0,0,0,0,0,0,0,0};
    for (int i = 0; i < 64; ++i) { int e = (tok[base + i] * 5099) & 7; c[e]++; }
    #pragma unroll
    for (int e = 0; e < 8; ++e) cnt[t][e] = c[e];
    __syncthreads();
    if (t < 8) {
        int run = 0;
        for (int j = 0; j < 256; ++j) { int v = cnt[j][t]; cnt[j][t] = run; run += v; }
    }
    __syncthreads();
    int run[8];
    #pragma unroll
    for (int e = 0; e < 8; ++e) run[e] = cnt[t][e];
    for (int i = 0; i < 64; ++i) {
        int s = base + i;
        int e = (tok[s] * 5099) & 7;
        int pos = run[e]++;
        if (pos < CAP) { int slot = e * CAP + pos; g_tok2slot[s] = slot; g_slot2tok[slot] = s; }
        else g_tok2slot[s] = DROPPED;
    }
}

// ---------------------------------------------------------------------------
// Dispatch: token-shift mix; write dk as bf16 [Ah|Al], dr as fp16 [Ah|Al]
// ---------------------------------------------------------------------------
__global__ void dispatch_kernel(const float* __restrict__ x,
                                const float* __restrict__ shift,
                                const float* __restrict__ maak,
                                const float* __restrict__ maar) {
    const int slot = blockIdx.x;
    const int j = threadIdx.x * 4;
    __nv_bfloat16* rk = g_dk_b + (size_t)slot * 2048;
    __half*        rr = g_dr_h + (size_t)slot * 2048;
    const int tokidx = g_slot2tok[slot];
    float4 dk, dr;
    if (tokidx < 0) {
        dk = dr = make_float4(0.f, 0.f, 0.f, 0.f);
    } else {
        const int b = tokidx / Tt;
        const int t = tokidx % Tt;
        float4 xv = *(const float4*)&x[(size_t)tokidx * Mm + j];
        float4 xp;
        if (t == 0) xp = *(const float4*)&shift[(size_t)b * Mm + j];
        else        xp = *(const float4*)&x[(size_t)(tokidx - 1) * Mm + j];
        float4 mk = *(const float4*)&maak[j];
        float4 mr = *(const float4*)&maar[j];
        float4 dx = make_float4(xp.x - xv.x, xp.y - xv.y, xp.z - xv.z, xp.w - xv.w);
        dk = make_float4(fmaf(dx.x, mk.x, xv.x), fmaf(dx.y, mk.y, xv.y),
                         fmaf(dx.z, mk.z, xv.z), fmaf(dx.w, mk.w, xv.w));
        dr = make_float4(fmaf(dx.x, mr.x, xv.x), fmaf(dx.y, mr.y, xv.y),
                         fmaf(dx.z, mr.z, xv.z), fmaf(dx.w, mr.w, xv.w));
    }
    // bf16 split for dk
    {
        __nv_bfloat16 h0 = __float2bfloat16(dk.x), h1 = __float2bfloat16(dk.y);
        __nv_bfloat16 h2 = __float2bfloat16(dk.z), h3 = __float2bfloat16(dk.w);
        __nv_bfloat16 l0 = __float2bfloat16(dk.x - __bfloat162float(h0));
        __nv_bfloat16 l1 = __float2bfloat16(dk.y - __bfloat162float(h1));
        __nv_bfloat16 l2 = __float2bfloat16(dk.z - __bfloat162float(h2));
        __nv_bfloat16 l3 = __float2bfloat16(dk.w - __bfloat162float(h3));
        *(__nv_bfloat162*)(rk + j)          = __halves2bfloat162(h0, h1);
        *(__nv_bfloat162*)(rk + j + 2)      = __halves2bfloat162(h2, h3);
        *(__nv_bfloat162*)(rk + 1024 + j)     = __halves2bfloat162(l0, l1);
        *(__nv_bfloat162*)(rk + 1024 + j + 2) = __halves2bfloat162(l2, l3);
    }
    // fp16 split for dr
    {
        __half h0 = __float2half(dr.x), h1 = __float2half(dr.y);
        __half h2 = __float2half(dr.z), h3 = __float2half(dr.w);
        __half l0 = __float2half(dr.x - __half2float(h0));
        __half l1 = __float2half(dr.y - __half2float(h1));
        __half l2 = __float2half(dr.z - __half2float(h2));
        __half l3 = __float2half(dr.w - __half2float(h3));
        *(__half2*)(rr + j)          = __halves2half2(h0, h1);
        *(__half2*)(rr + j + 2)      = __halves2half2(h2, h3);
        *(__half2*)(rr + 1024 + j)     = __halves2half2(l0, l1);
        *(__half2*)(rr + 1024 + j + 2) = __halves2half2(l2, l3);
    }
}

// ---------------------------------------------------------------------------
// Weight transpose: W [E][K][N] fp32 -> N-major.
// bf16 split variant (Wk) and fp16 hi-only variant (Wv, Wr).
// ---------------------------------------------------------------------------
__global__ void wconv_bf16_kernel(const float* __restrict__ W,
                                  __nv_bfloat16* __restrict__ out, int K, int N) {
    __shared__ float tile[32][33];
    const int e = blockIdx.z;
    const float* Wp = W + (size_t)e * K * N;
    __nv_bfloat16* op = out + (size_t)e * N * 2 * K;
    const int k0 = blockIdx.y * 32, n0 = blockIdx.x * 32;
    const int tx = threadIdx.x, ty = threadIdx.y;
    #pragma unroll
    for (int i = 0; i < 32; i += 8)
        tile[ty + i][tx] = Wp[(size_t)(k0 + ty + i) * N + n0 + tx];
    __syncthreads();
    #pragma unroll
    for (int i = 0; i < 32; i += 8) {
        float v = tile[tx][ty + i];
        __nv_bfloat16 hi = __float2bfloat16(v);
        __nv_bfloat16 lo = __float2bfloat16(v - __bfloat162float(hi));
        size_t base = (size_t)(n0 + ty + i) * 2 * K + k0 + tx;
        op[base]     = hi;
        op[base + K] = lo;
    }
}
__global__ void wconv_fp16_kernel(const float* __restrict__ W,
                                  __half* __restrict__ out, int K, int N) {
    __shared__ float tile[32][33];
    const int e = blockIdx.z;
    const float* Wp = W + (size_t)e * K * N;
    __half* op = out + (size_t)e * N * K;
    const int k0 = blockIdx.y * 32, n0 = blockIdx.x * 32;
    const int tx = threadIdx.x, ty = threadIdx.y;
    #pragma unroll
    for (int i = 0; i < 32; i += 8)
        tile[ty + i][tx] = Wp[(size_t)(k0 + ty + i) * N + n0 + tx];
    __syncthreads();
    #pragma unroll
    for (int i = 0; i < 32; i += 8)
        op[(size_t)(n0 + ty + i) * K + k0 + tx] = __float2half(tile[tx][ty + i]);
}

// ---------------------------------------------------------------------------
// HMMA GEMM with chunked split-LUT.
//  MODE 0 (3-term): KT=3*TCH, K=TCH*32; A=[Ah|Al] (stride 2K), B=[Bh|Bl] (stride 2K)
//      chunk seg 0: Ah*Bh, seg 1: Ah*Bl, seg 2: Al*Bh
//  MODE 1 (2-term): KT=2*TCH; A=[Ah|Al] (stride 2K), B=[Bh] (stride K), B reread.
//  EPI 0: relu^2 -> fp16 split [Hh|Hl] into Cb (stride 2N). EPI 1: f32 copy.
//  EPI 2: sigmoid f32.
// ---------------------------------------------------------------------------
constexpr int STAGE_B  = 16384;          // A 8KB + B 8KB
constexpr int GEMM_SMEM = 4 * STAGE_B;   // 64 KB

template<int EPI, int MODE, int TCH, bool HALF>
__global__ void __launch_bounds__(256, 2)
gemm_mma(const void* __restrict__ Ag, const void* __restrict__ Bg,
         float* __restrict__ Cf, __half* __restrict__ Cb, int N) {
    constexpr int K  = TCH * 32;
    constexpr int KT = (MODE == 0 ? 3 : 2) * TCH;
    constexpr int SA = 2 * K;                     // A row stride (elems)
    constexpr int SB = (MODE == 0 ? 2 * K : K);   // B row stride (elems)

    extern __shared__ __align__(1024) char smem[];
    const uint32_t sb = smem_u32(smem);
    const int tid = threadIdx.x;
    const int lane = tid & 31, warp = tid >> 5;
    const int wm = warp & 3, wn = warp >> 2;
    const int e = blockIdx.z;
    const int bm = blockIdx.y * 128, bn = blockIdx.x * 128;

    const char* A = (const char*)Ag + ((size_t)e * 2048 + bm) * SA * 2;
    const char* B = (const char*)Bg + ((size_t)e * N + bn) * SB * 2;

    const int r0u = tid >> 2,         c0u = tid & 3;
    const int r1u = (tid + 256) >> 2, c1u = tid & 3;
    const uint32_t dA0 = (uint32_t)(r0u * 64 + ((c0u ^ ((r0u >> 1) & 3)) << 4));
    const uint32_t dA1 = (uint32_t)(r1u * 64 + ((c1u ^ ((r1u >> 1) & 3)) << 4));
    const uint32_t cb0 = (uint32_t)(c0u * 16), cb1 = (uint32_t)(c1u * 16);

    auto load_stage = [&](int st, int kt) {
        int acolB, bcolB;       // byte offsets of chunk within row
        if (MODE == 0) {
            int seg = kt / TCH, r = kt - seg * TCH;
            acolB = r * 64 + (seg == 2 ? K * 2 : 0);
            bcolB = r * 64 + (seg == 1 ? K * 2 : 0);
        } else {
            acolB = kt * 64;
            bcolB = (kt >= TCH ? (kt - TCH) : kt) * 64;
        }
        uint32_t b = sb + st * STAGE_B;
        cp16(b + dA0,        A + (size_t)r0u * (SA * 2) + acolB + cb0);
        cp16(b + dA1,        A + (size_t)r1u * (SA * 2) + acolB + cb1);
        cp16(b + 8192 + dA0, B + (size_t)r0u * (SB * 2) + bcolB + cb0);
        cp16(b + 8192 + dA1, B + (size_t)r1u * (SB * 2) + bcolB + cb1);
    };

    const int rowA = wm * 32 + (lane & 15);
    const uint32_t aOff = (uint32_t)(rowA * 64 +
                          (((lane >> 4) ^ ((rowA >> 1) & 3)) << 4));
    const int rowB = wn * 64 + (lane & 7) + ((lane >> 4) << 3);
    const uint32_t bOff = (uint32_t)(rowB * 64 +
                          ((((lane >> 3) & 1) ^ ((rowB >> 1) & 3)) << 4));

    float acc[2][8][4];
    #pragma unroll
    for (int i = 0; i < 2; ++i)
        #pragma unroll
        for (int j = 0; j < 8; ++j)
            #pragma unroll
            for (int k = 0; k < 4; ++k) acc[i][j][k] = 0.f;

    load_stage(0, 0); CP_COMMIT();
    load_stage(1, 1); CP_COMMIT();
    load_stage(2, 2); CP_COMMIT();

    for (int kt = 0; kt < KT; ++kt) {
        CP_WAIT2();
        __syncthreads();
        if (kt + 3 < KT) load_stage((kt + 3) & 3, kt + 3);
        CP_COMMIT();

        const uint32_t stb = sb + (kt & 3) * STAGE_B;
        #pragma unroll
        for (int ks = 0; ks < 2; ++ks) {
            const uint32_t kx = ks * 32;
            uint32_t a[2][4];
            #pragma unroll
            for (int mi = 0; mi < 2; ++mi)
                LDSM_X4(a[mi], (stb + aOff + mi * 1024) ^ kx);
            uint32_t b[4][4];
            #pragma unroll
            for (int nf2 = 0; nf2 < 4; ++nf2)
                LDSM_X4(b[nf2], (stb + 8192 + bOff + nf2 * 1024) ^ kx);
            #pragma unroll
            for (int mi = 0; mi < 2; ++mi)
                #pragma unroll
                for (int nf2 = 0; nf2 < 4; ++nf2) {
                    if (HALF) {
                        mma_fp16(acc[mi][nf2 * 2 + 0], a[mi], b[nf2][0], b[nf2][1]);
                        mma_fp16(acc[mi][nf2 * 2 + 1], a[mi], b[nf2][2], b[nf2][3]);
                    } else {
                        mma_bf16(acc[mi][nf2 * 2 + 0], a[mi], b[nf2][0], b[nf2][1]);
                        mma_bf16(acc[mi][nf2 * 2 + 1], a[mi], b[nf2][2], b[nf2][3]);
                    }
                }
        }
    }

    // Epilogue
    #pragma unroll
    for (int mi = 0; mi < 2; ++mi) {
        #pragma unroll
        for (int nf = 0; nf < 8; ++nf) {
            const float* c = acc[mi][nf];
            const int col = bn + wn * 64 + nf * 8 + (lane & 3) * 2;
            const int row0 = bm + wm * 32 + mi * 16 + (lane >> 2);
            #pragma unroll
            for (int hh = 0; hh < 2; ++hh) {
                const int row = row0 + hh * 8;
                float v0 = c[hh * 2 + 0], v1 = c[hh * 2 + 1];
                if (EPI == 0) {
                    v0 = v0 > 0.f ? v0 * v0 : 0.f;
                    v1 = v1 > 0.f ? v1 * v1 : 0.f;
                    __half h0 = __float2half(v0);
                    __half h1 = __float2half(v1);
                    __half l0 = __float2half(v0 - __half2float(h0));
                    __half l1 = __float2half(v1 - __half2float(h1));
                    __half* p = Cb + ((size_t)e * 2048 + row) * (size_t)(2 * N) + col;
                    *(__half2*)p       = __halves2half2(h0, h1);
                    *(__half2*)(p + N) = __halves2half2(l0, l1);
                } else {
                    if (EPI == 2) {
                        v0 = 1.f / (1.f + __expf(-v0));
                        v1 = 1.f / (1.f + __expf(-v1));
                    }
                    float* p = Cf + ((size_t)e * 2048 + row) * (size_t)N + col;
                    *(float2*)p = make_float2(v0, v1);
                }
            }
        }
    }
}

// ---------------------------------------------------------------------------
// Combine + shift
// ---------------------------------------------------------------------------
__global__ void combine_kernel(float* __restrict__ out) {
    const int s = blockIdx.x;
    const int j = threadIdx.x * 4;
    const size_t oo = (size_t)s * Mm + j;
    const int slot = g_tok2slot[s];
    float4 o = make_float4(0.f, 0.f, 0.f, 0.f);
    if (slot < ECAP) {
        const size_t so = (size_t)slot * Mm + j;
        float4 rv = *(const float4*)&g_r[so];
        float4 kv = *(const float4*)&g_kv[so];
        o = make_float4(rv.x * kv.x, rv.y * kv.y, rv.z * kv.z, rv.w * kv.w);
    }
    *(float4*)&out[oo] = o;
}
__global__ void shift_kernel(const float* __restrict__ x, float* __restrict__ out) {
    const int b = blockIdx.x;
    const int j = threadIdx.x * 4;
    *(float4*)&out[(size_t)Ss * Mm + (size_t)b * Mm + j] =
        *(const float4*)&x[((size_t)b * Tt + (Tt - 1)) * Mm + j];
}

// ---------------------------------------------------------------------------
// Host
// ---------------------------------------------------------------------------
extern "C" void kernel_launch(void* const* d_in, const int* in_sizes, int n_in,
                              void* d_out, int out_size) {
    const float* x     = (const float*)d_in[0];
    const int*   tok   = (const int*)  d_in[1];
    const float* shift = (const float*)d_in[2];
    const float* maak  = (const float*)d_in[3];
    const float* maar  = (const float*)d_in[4];
    const float* Wk    = (const float*)d_in[5];
    const float* Wv    = (const float*)d_in[6];
    const float* Wr    = (const float*)d_in[7];
    float* out = (float*)d_out;

    void *dkb, *drh, *hh, *wkb, *wvh, *wrh, *kvp, *rp;
    cudaGetSymbolAddress(&dkb, g_dk_b);
    cudaGetSymbolAddress(&drh, g_dr_h);
    cudaGetSymbolAddress(&hh,  g_h_h);
    cudaGetSymbolAddress(&wkb, g_Wk_b);
    cudaGetSymbolAddress(&wvh, g_Wv_h);
    cudaGetSymbolAddress(&wrh, g_Wr_h);
    cudaGetSymbolAddress(&kvp, g_kv);
    cudaGetSymbolAddress(&rp,  g_r);

    cudaFuncSetAttribute((const void*)gemm_mma<0, 0, 32, false>,
                         cudaFuncAttributeMaxDynamicSharedMemorySize, GEMM_SMEM);
    cudaFuncSetAttribute((const void*)gemm_mma<1, 1, 64, true>,
                         cudaFuncAttributeMaxDynamicSharedMemorySize, GEMM_SMEM);
    cudaFuncSetAttribute((const void*)gemm_mma<2, 1, 32, true>,
                         cudaFuncAttributeMaxDynamicSharedMemorySize, GEMM_SMEM);

    route_kernel<<<1, 256>>>(tok);
    dispatch_kernel<<<ECAP, 256>>>(x, shift, maak, maar);
    wconv_bf16_kernel<<<dim3(64, 32, 8), dim3(32, 8)>>>(Wk, (__nv_bfloat16*)wkb, 1024, 2048);
    wconv_fp16_kernel<<<dim3(32, 64, 8), dim3(32, 8)>>>(Wv, (__half*)wvh, 2048, 1024);
    wconv_fp16_kernel<<<dim3(32, 32, 8), dim3(32, 8)>>>(Wr, (__half*)wrh, 1024, 1024);

    // h = relu^2(dk @ Wk): bf16 3-term, K=1024 (KT=96); epi writes fp16 [Hh|Hl]
    gemm_mma<0, 0, 32, false><<<dim3(16, 16, 8), 256, GEMM_SMEM>>>(
        dkb, wkb, nullptr, (__half*)hh, 2048);
    // kv = h @ Wv: fp16 2-term, K=2048 (KT=128)
    gemm_mma<1, 1, 64, true><<<dim3(8, 16, 8), 256, GEMM_SMEM>>>(
        hh, wvh, (float*)kvp, nullptr, 1024);
    // r = sigmoid(dr @ Wr): fp16 2-term, K=1024 (KT=64)
    gemm_mma<2, 1, 32, true><<<dim3(8, 16, 8), 256, GEMM_SMEM>>>(
        drh, wrh, (float*)rp, nullptr, 1024);

    combine_kernel<<<Ss, 256>>>(out);
    if ((size_t)out_size >= (size_t)Ss * Mm + (size_t)Bb * Mm)
        shift_kernel<<<Bb, 256>>>(x, out);
}

// round 5
// speedup vs baseline: 3.8292x; 1.1008x over previous
#include <cuda_runtime.h>
#include <cuda_fp16.h>
#include <stdint.h>

// ---------------------------------------------------------------------------
// Problem constants
// ---------------------------------------------------------------------------
#define Bb 8
#define Tt 2048
#define Mm 1024
#define Ff 2048
#define Ee 8
#define Ss 16384
#define CAP 2048
#define ECAP 16384
#define DROPPED 0x7FFFFFFF

// All-fp16 2-term scheme: A = [Ah | Al] (exact to ~2^-22), B = hi-only fp16.
//  dk  : fp16 [ECAP][2048]
//  dr  : fp16 [ECAP][2048]
//  h   : fp16 [ECAP][4096]  = [Hh | Hl]
//  Wk' : fp16 [E][2048][1024]  (N-major)
//  Wv' : fp16 [E][1024][2048]
//  Wr' : fp16 [E][1024][1024]
__device__ __align__(128) __half g_dk_h[(size_t)ECAP * 2048];
__device__ __align__(128) __half g_dr_h[(size_t)ECAP * 2048];
__device__ __align__(128) __half g_h_h [(size_t)ECAP * 4096];
__device__ __align__(128) __half g_Wk_h[(size_t)Ee * 2048 * 1024];
__device__ __align__(128) __half g_Wv_h[(size_t)Ee * 1024 * 2048];
__device__ __align__(128) __half g_Wr_h[(size_t)Ee * 1024 * 1024];
__device__ float g_kv[(size_t)ECAP * Mm];
__device__ float g_r [(size_t)ECAP * Mm];
__device__ int   g_slot2tok[ECAP];
__device__ int   g_tok2slot[Ss];

// ---------------------------------------------------------------------------
// PTX helpers
// ---------------------------------------------------------------------------
__device__ __forceinline__ uint32_t smem_u32(const void* p) {
    uint32_t a;
    asm("{ .reg .u64 t; cvta.to.shared.u64 t, %1; cvt.u32.u64 %0, t; }" : "=r"(a) : "l"(p));
    return a;
}
__device__ __forceinline__ void cp16(uint32_t s, const void* g) {
    asm volatile("cp.async.cg.shared.global [%0], [%1], 16;" :: "r"(s), "l"(g) : "memory");
}
#define CP_COMMIT() asm volatile("cp.async.commit_group;" ::: "memory")
#define CP_WAIT2()  asm volatile("cp.async.wait_group 2;" ::: "memory")

#define LDSM_X4(r, a) \
    asm volatile("ldmatrix.sync.aligned.m8n8.x4.shared.b16 {%0,%1,%2,%3}, [%4];" \
        : "=r"((r)[0]), "=r"((r)[1]), "=r"((r)[2]), "=r"((r)[3]) : "r"(a))

__device__ __forceinline__ void mma_fp16(float* c, const uint32_t* a,
                                         uint32_t b0, uint32_t b1) {
    asm volatile(
        "mma.sync.aligned.m16n8k16.row.col.f32.f16.f16.f32 "
        "{%0,%1,%2,%3}, {%4,%5,%6,%7}, {%8,%9}, {%0,%1,%2,%3};"
        : "+f"(c[0]), "+f"(c[1]), "+f"(c[2]), "+f"(c[3])
        : "r"(a[0]), "r"(a[1]), "r"(a[2]), "r"(a[3]), "r"(b0), "r"(b1));
}

// ---------------------------------------------------------------------------
// Routing: exact order-preserving per-expert positions
// ---------------------------------------------------------------------------
__global__ void route_kernel(const int* __restrict__ tok) {
    __shared__ int cnt[256][8];
    const int t = threadIdx.x;
    for (int i = t; i < ECAP; i += 256) g_slot2tok[i] = -1;
    const int base = t * 64;
    int c[8] = {0,0,0,0,0,0,0,0};
    for (int i = 0; i < 64; ++i) { int e = (tok[base + i] * 5099) & 7; c[e]++; }
    #pragma unroll
    for (int e = 0; e < 8; ++e) cnt[t][e] = c[e];
    __syncthreads();
    if (t < 8) {
        int run = 0;
        for (int j = 0; j < 256; ++j) { int v = cnt[j][t]; cnt[j][t] = run; run += v; }
    }
    __syncthreads();
    int run[8];
    #pragma unroll
    for (int e = 0; e < 8; ++e) run[e] = cnt[t][e];
    for (int i = 0; i < 64; ++i) {
        int s = base + i;
        int e = (tok[s] * 5099) & 7;
        int pos = run[e]++;
        if (pos < CAP) { int slot = e * CAP + pos; g_tok2slot[s] = slot; g_slot2tok[slot] = s; }
        else g_tok2slot[s] = DROPPED;
    }
}

// ---------------------------------------------------------------------------
// Dispatch: token-shift mix; dk & dr as fp16 [Ah|Al]
// ---------------------------------------------------------------------------
__device__ __forceinline__ void fp16_split4(__half* row, int j, float4 v) {
    __half h0 = __float2half(v.x), h1 = __float2half(v.y);
    __half h2 = __float2half(v.z), h3 = __float2half(v.w);
    __half l0 = __float2half(v.x - __half2float(h0));
    __half l1 = __float2half(v.y - __half2float(h1));
    __half l2 = __float2half(v.z - __half2float(h2));
    __half l3 = __float2half(v.w - __half2float(h3));
    *(__half2*)(row + j)            = __halves2half2(h0, h1);
    *(__half2*)(row + j + 2)        = __halves2half2(h2, h3);
    *(__half2*)(row + 1024 + j)     = __halves2half2(l0, l1);
    *(__half2*)(row + 1024 + j + 2) = __halves2half2(l2, l3);
}

__global__ void dispatch_kernel(const float* __restrict__ x,
                                const float* __restrict__ shift,
                                const float* __restrict__ maak,
                                const float* __restrict__ maar) {
    const int slot = blockIdx.x;
    const int j = threadIdx.x * 4;
    __half* rk = g_dk_h + (size_t)slot * 2048;
    __half* rr = g_dr_h + (size_t)slot * 2048;
    const int tokidx = g_slot2tok[slot];
    float4 dk, dr;
    if (tokidx < 0) {
        dk = dr = make_float4(0.f, 0.f, 0.f, 0.f);
    } else {
        const int b = tokidx / Tt;
        const int t = tokidx % Tt;
        float4 xv = *(const float4*)&x[(size_t)tokidx * Mm + j];
        float4 xp;
        if (t == 0) xp = *(const float4*)&shift[(size_t)b * Mm + j];
        else        xp = *(const float4*)&x[(size_t)(tokidx - 1) * Mm + j];
        float4 mk = *(const float4*)&maak[j];
        float4 mr = *(const float4*)&maar[j];
        float4 dx = make_float4(xp.x - xv.x, xp.y - xv.y, xp.z - xv.z, xp.w - xv.w);
        dk = make_float4(fmaf(dx.x, mk.x, xv.x), fmaf(dx.y, mk.y, xv.y),
                         fmaf(dx.z, mk.z, xv.z), fmaf(dx.w, mk.w, xv.w));
        dr = make_float4(fmaf(dx.x, mr.x, xv.x), fmaf(dx.y, mr.y, xv.y),
                         fmaf(dx.z, mr.z, xv.z), fmaf(dx.w, mr.w, xv.w));
    }
    fp16_split4(rk, j, dk);
    fp16_split4(rr, j, dr);
}

// ---------------------------------------------------------------------------
// Weight transpose: W [E][K][N] fp32 -> W' [E][N][K] fp16 (hi only)
// ---------------------------------------------------------------------------
__global__ void wconv_fp16_kernel(const float* __restrict__ W,
                                  __half* __restrict__ out, int K, int N) {
    __shared__ float tile[32][33];
    const int e = blockIdx.z;
    const float* Wp = W + (size_t)e * K * N;
    __half* op = out + (size_t)e * N * K;
    const int k0 = blockIdx.y * 32, n0 = blockIdx.x * 32;
    const int tx = threadIdx.x, ty = threadIdx.y;
    #pragma unroll
    for (int i = 0; i < 32; i += 8)
        tile[ty + i][tx] = Wp[(size_t)(k0 + ty + i) * N + n0 + tx];
    __syncthreads();
    #pragma unroll
    for (int i = 0; i < 32; i += 8)
        op[(size_t)(n0 + ty + i) * K + k0 + tx] = __float2half(tile[tx][ty + i]);
}

// ---------------------------------------------------------------------------
// fp16 HMMA GEMM, 2-term A-split.
// Block tile 128x128, 4 warps, each warp 64x64 (4M x 8N fragments).
// A row: [Ah|Al], 2K elems. B row: K elems. KT = 2*TCH chunks of 32 k-elems.
// EPI 0: relu^2 -> fp16 split [Hh|Hl]; EPI 1: f32 copy; EPI 2: sigmoid f32.
// ---------------------------------------------------------------------------
constexpr int STAGE_B   = 16384;          // A 8KB + B 8KB
constexpr int GEMM_SMEM = 4 * STAGE_B;    // 64 KB

template<int EPI, int TCH>
__global__ void __launch_bounds__(128, 2)
gemm_mma(const __half* __restrict__ Ag, const __half* __restrict__ Bg,
         float* __restrict__ Cf, __half* __restrict__ Cb, int N) {
    constexpr int K  = TCH * 32;
    constexpr int KT = 2 * TCH;
    constexpr int AROW_B = 4 * K;     // bytes: 2 terms * K elems * 2B
    constexpr int BROW_B = 2 * K;     // bytes

    extern __shared__ __align__(1024) char smem[];
    const uint32_t sb = smem_u32(smem);
    const int tid = threadIdx.x;
    const int lane = tid & 31, warp = tid >> 5;
    const int wm = warp & 1, wn = warp >> 1;
    const int e = blockIdx.z;
    const int bm = blockIdx.y * 128, bn = blockIdx.x * 128;

    const char* A = (const char*)Ag + ((size_t)e * 2048 + bm) * AROW_B;
    const char* B = (const char*)Bg + ((size_t)e * N + bn) * BROW_B;

    // loader: 128 threads, 4 rows each (stride 32) x 16B, for A and B tiles
    const int lr = tid >> 2, lc = tid & 3;
    const uint32_t dL = (uint32_t)(lr * 64 + ((lc ^ ((lr >> 1) & 3)) << 4));
    const uint32_t cbL = (uint32_t)(lc * 16);

    auto load_stage = [&](int st, int kt) {
        const int acolB = kt * 64;
        const int bcolB = (kt >= TCH ? kt - TCH : kt) * 64;
        uint32_t b = sb + st * STAGE_B;
        #pragma unroll
        for (int i = 0; i < 4; ++i) {
            cp16(b + dL + i * 2048,
                 A + (size_t)(lr + i * 32) * AROW_B + acolB + cbL);
            cp16(b + 8192 + dL + i * 2048,
                 B + (size_t)(lr + i * 32) * BROW_B + bcolB + cbL);
        }
    };

    // ldmatrix offsets (mi/nf2 add 16 rows = +1024B; swizzle unit invariant)
    const int rowA0 = wm * 64 + (lane & 15);
    const uint32_t aOff = (uint32_t)(rowA0 * 64 +
                          (((lane >> 4) ^ ((rowA0 >> 1) & 3)) << 4));
    const int rowB0 = wn * 64 + (lane & 7) + ((lane >> 4) << 3);
    const uint32_t bOff = (uint32_t)(rowB0 * 64 +
                          ((((lane >> 3) & 1) ^ ((rowB0 >> 1) & 3)) << 4));

    float acc[4][8][4];
    #pragma unroll
    for (int i = 0; i < 4; ++i)
        #pragma unroll
        for (int j = 0; j < 8; ++j)
            #pragma unroll
            for (int k = 0; k < 4; ++k) acc[i][j][k] = 0.f;

    load_stage(0, 0); CP_COMMIT();
    load_stage(1, 1); CP_COMMIT();
    load_stage(2, 2); CP_COMMIT();

    for (int kt = 0; kt < KT; ++kt) {
        CP_WAIT2();
        __syncthreads();
        if (kt + 3 < KT) load_stage((kt + 3) & 3, kt + 3);
        CP_COMMIT();

        const uint32_t stb = sb + (kt & 3) * STAGE_B;
        #pragma unroll
        for (int ks = 0; ks < 2; ++ks) {
            const uint32_t kx = ks * 32;
            uint32_t a[4][4];
            #pragma unroll
            for (int mi = 0; mi < 4; ++mi)
                LDSM_X4(a[mi], (stb + aOff + mi * 1024) ^ kx);
            uint32_t b[4][4];
            #pragma unroll
            for (int nf2 = 0; nf2 < 4; ++nf2)
                LDSM_X4(b[nf2], (stb + 8192 + bOff + nf2 * 1024) ^ kx);
            #pragma unroll
            for (int mi = 0; mi < 4; ++mi)
                #pragma unroll
                for (int nf2 = 0; nf2 < 4; ++nf2) {
                    mma_fp16(acc[mi][nf2 * 2 + 0], a[mi], b[nf2][0], b[nf2][1]);
                    mma_fp16(acc[mi][nf2 * 2 + 1], a[mi], b[nf2][2], b[nf2][3]);
                }
        }
    }

    // Epilogue
    #pragma unroll
    for (int mi = 0; mi < 4; ++mi) {
        #pragma unroll
        for (int nf = 0; nf < 8; ++nf) {
            const float* c = acc[mi][nf];
            const int col = bn + wn * 64 + nf * 8 + (lane & 3) * 2;
            const int row0 = bm + wm * 64 + mi * 16 + (lane >> 2);
            #pragma unroll
            for (int hh = 0; hh < 2; ++hh) {
                const int row = row0 + hh * 8;
                float v0 = c[hh * 2 + 0], v1 = c[hh * 2 + 1];
                if (EPI == 0) {
                    v0 = v0 > 0.f ? v0 * v0 : 0.f;
                    v1 = v1 > 0.f ? v1 * v1 : 0.f;
                    __half h0 = __float2half(v0);
                    __half h1 = __float2half(v1);
                    __half l0 = __float2half(v0 - __half2float(h0));
                    __half l1 = __float2half(v1 - __half2float(h1));
                    __half* p = Cb + ((size_t)e * 2048 + row) * (size_t)(2 * N) + col;
                    *(__half2*)p       = __halves2half2(h0, h1);
                    *(__half2*)(p + N) = __halves2half2(l0, l1);
                } else {
                    if (EPI == 2) {
                        v0 = 1.f / (1.f + __expf(-v0));
                        v1 = 1.f / (1.f + __expf(-v1));
                    }
                    float* p = Cf + ((size_t)e * 2048 + row) * (size_t)N + col;
                    *(float2*)p = make_float2(v0, v1);
                }
            }
        }
    }
}

// ---------------------------------------------------------------------------
// Combine + shift
// ---------------------------------------------------------------------------
__global__ void combine_kernel(float* __restrict__ out) {
    const int s = blockIdx.x;
    const int j = threadIdx.x * 4;
    const size_t oo = (size_t)s * Mm + j;
    const int slot = g_tok2slot[s];
    float4 o = make_float4(0.f, 0.f, 0.f, 0.f);
    if (slot < ECAP) {
        const size_t so = (size_t)slot * Mm + j;
        float4 rv = *(const float4*)&g_r[so];
        float4 kv = *(const float4*)&g_kv[so];
        o = make_float4(rv.x * kv.x, rv.y * kv.y, rv.z * kv.z, rv.w * kv.w);
    }
    *(float4*)&out[oo] = o;
}
__global__ void shift_kernel(const float* __restrict__ x, float* __restrict__ out) {
    const int b = blockIdx.x;
    const int j = threadIdx.x * 4;
    *(float4*)&out[(size_t)Ss * Mm + (size_t)b * Mm + j] =
        *(const float4*)&x[((size_t)b * Tt + (Tt - 1)) * Mm + j];
}

// ---------------------------------------------------------------------------
// Host
// ---------------------------------------------------------------------------
extern "C" void kernel_launch(void* const* d_in, const int* in_sizes, int n_in,
                              void* d_out, int out_size) {
    const float* x     = (const float*)d_in[0];
    const int*   tok   = (const int*)  d_in[1];
    const float* shift = (const float*)d_in[2];
    const float* maak  = (const float*)d_in[3];
    const float* maar  = (const float*)d_in[4];
    const float* Wk    = (const float*)d_in[5];
    const float* Wv    = (const float*)d_in[6];
    const float* Wr    = (const float*)d_in[7];
    float* out = (float*)d_out;

    void *dkh, *drh, *hh, *wkh, *wvh, *wrh, *kvp, *rp;
    cudaGetSymbolAddress(&dkh, g_dk_h);
    cudaGetSymbolAddress(&drh, g_dr_h);
    cudaGetSymbolAddress(&hh,  g_h_h);
    cudaGetSymbolAddress(&wkh, g_Wk_h);
    cudaGetSymbolAddress(&wvh, g_Wv_h);
    cudaGetSymbolAddress(&wrh, g_Wr_h);
    cudaGetSymbolAddress(&kvp, g_kv);
    cudaGetSymbolAddress(&rp,  g_r);

    cudaFuncSetAttribute((const void*)gemm_mma<0, 32>,
                         cudaFuncAttributeMaxDynamicSharedMemorySize, GEMM_SMEM);
    cudaFuncSetAttribute((const void*)gemm_mma<1, 64>,
                         cudaFuncAttributeMaxDynamicSharedMemorySize, GEMM_SMEM);
    cudaFuncSetAttribute((const void*)gemm_mma<2, 32>,
                         cudaFuncAttributeMaxDynamicSharedMemorySize, GEMM_SMEM);

    route_kernel<<<1, 256>>>(tok);
    dispatch_kernel<<<ECAP, 256>>>(x, shift, maak, maar);
    wconv_fp16_kernel<<<dim3(64, 32, 8), dim3(32, 8)>>>(Wk, (__half*)wkh, 1024, 2048);
    wconv_fp16_kernel<<<dim3(32, 64, 8), dim3(32, 8)>>>(Wv, (__half*)wvh, 2048, 1024);
    wconv_fp16_kernel<<<dim3(32, 32, 8), dim3(32, 8)>>>(Wr, (__half*)wrh, 1024, 1024);

    // h = relu^2(dk @ Wk): K=1024, KT=64; writes fp16 [Hh|Hl]
    gemm_mma<0, 32><<<dim3(16, 16, 8), 128, GEMM_SMEM>>>(
        (const __half*)dkh, (const __half*)wkh, nullptr, (__half*)hh, 2048);
    // kv = h @ Wv: K=2048, KT=128
    gemm_mma<1, 64><<<dim3(8, 16, 8), 128, GEMM_SMEM>>>(
        (const __half*)hh, (const __half*)wvh, (float*)kvp, nullptr, 1024);
    // r = sigmoid(dr @ Wr): K=1024, KT=64
    gemm_mma<2, 32><<<dim3(8, 16, 8), 128, GEMM_SMEM>>>(
        (const __half*)drh, (const __half*)wrh, (float*)rp, nullptr, 1024);

    combine_kernel<<<Ss, 256>>>(out);
    if ((size_t)out_size >= (size_t)Ss * Mm + (size_t)Bb * Mm)
        shift_kernel<<<Bb, 256>>>(x, out);
}

// round 6
// speedup vs baseline: 4.3356x; 1.1323x over previous
#include <cuda_runtime.h>
#include <cuda_fp16.h>
#include <stdint.h>

// ---------------------------------------------------------------------------
// Problem constants
// ---------------------------------------------------------------------------
#define Bb 8
#define Tt 2048
#define Mm 1024
#define Ff 2048
#define Ee 8
#define Ss 16384
#define CAP 2048
#define ECAP 16384
#define DROPPED 0x7FFFFFFF

// fp16 2-term scheme: A = [Ah | Al] (exact to ~2^-22), B = hi-only fp16.
__device__ __align__(128) __half g_dk_h[(size_t)ECAP * 2048];
__device__ __align__(128) __half g_dr_h[(size_t)ECAP * 2048];
__device__ __align__(128) __half g_h_h [(size_t)ECAP * 4096];
__device__ __align__(128) __half g_Wk_h[(size_t)Ee * 2048 * 1024];
__device__ __align__(128) __half g_Wv_h[(size_t)Ee * 1024 * 2048];
__device__ __align__(128) __half g_Wr_h[(size_t)Ee * 1024 * 1024];
__device__ float g_kv[(size_t)ECAP * Mm];
__device__ float g_r [(size_t)ECAP * Mm];
__device__ int   g_slot2tok[ECAP];
__device__ int   g_tok2slot[Ss];

// ---------------------------------------------------------------------------
// PTX helpers
// ---------------------------------------------------------------------------
__device__ __forceinline__ uint32_t smem_u32(const void* p) {
    uint32_t a;
    asm("{ .reg .u64 t; cvta.to.shared.u64 t, %1; cvt.u32.u64 %0, t; }" : "=r"(a) : "l"(p));
    return a;
}
__device__ __forceinline__ void cp16(uint32_t s, const void* g) {
    asm volatile("cp.async.cg.shared.global [%0], [%1], 16;" :: "r"(s), "l"(g) : "memory");
}
#define CP_COMMIT() asm volatile("cp.async.commit_group;" ::: "memory")
#define CP_WAIT2()  asm volatile("cp.async.wait_group 2;" ::: "memory")

#define LDSM_X4(r, a) \
    asm volatile("ldmatrix.sync.aligned.m8n8.x4.shared.b16 {%0,%1,%2,%3}, [%4];" \
        : "=r"((r)[0]), "=r"((r)[1]), "=r"((r)[2]), "=r"((r)[3]) : "r"(a))

__device__ __forceinline__ void mma_fp16(float* c, const uint32_t* a,
                                         uint32_t b0, uint32_t b1) {
    asm volatile(
        "mma.sync.aligned.m16n8k16.row.col.f32.f16.f16.f32 "
        "{%0,%1,%2,%3}, {%4,%5,%6,%7}, {%8,%9}, {%0,%1,%2,%3};"
        : "+f"(c[0]), "+f"(c[1]), "+f"(c[2]), "+f"(c[3])
        : "r"(a[0]), "r"(a[1]), "r"(a[2]), "r"(a[3]), "r"(b0), "r"(b1));
}

// ---------------------------------------------------------------------------
// Routing: exact order-preserving per-expert positions
// ---------------------------------------------------------------------------
__global__ void route_kernel(const int* __restrict__ tok) {
    __shared__ int cnt[256][8];
    const int t = threadIdx.x;
    for (int i = t; i < ECAP; i += 256) g_slot2tok[i] = -1;
    const int base = t * 64;
    int c[8] = {0,0,0,0,0,0,0,0};
    for (int i = 0; i < 64; ++i) { int e = (tok[base + i] * 5099) & 7; c[e]++; }
    #pragma unroll
    for (int e = 0; e < 8; ++e) cnt[t][e] = c[e];
    __syncthreads();
    if (t < 8) {
        int run = 0;
        for (int j = 0; j < 256; ++j) { int v = cnt[j][t]; cnt[j][t] = run; run += v; }
    }
    __syncthreads();
    int run[8];
    #pragma unroll
    for (int e = 0; e < 8; ++e) run[e] = cnt[t][e];
    for (int i = 0; i < 64; ++i) {
        int s = base + i;
        int e = (tok[s] * 5099) & 7;
        int pos = run[e]++;
        if (pos < CAP) { int slot = e * CAP + pos; g_tok2slot[s] = slot; g_slot2tok[slot] = s; }
        else g_tok2slot[s] = DROPPED;
    }
}

// ---------------------------------------------------------------------------
// Dispatch: token-shift mix; dk & dr as fp16 [Ah|Al]
// ---------------------------------------------------------------------------
__device__ __forceinline__ void fp16_split4(__half* row, int j, float4 v) {
    __half h0 = __float2half(v.x), h1 = __float2half(v.y);
    __half h2 = __float2half(v.z), h3 = __float2half(v.w);
    __half l0 = __float2half(v.x - __half2float(h0));
    __half l1 = __float2half(v.y - __half2float(h1));
    __half l2 = __float2half(v.z - __half2float(h2));
    __half l3 = __float2half(v.w - __half2float(h3));
    *(__half2*)(row + j)            = __halves2half2(h0, h1);
    *(__half2*)(row + j + 2)        = __halves2half2(h2, h3);
    *(__half2*)(row + 1024 + j)     = __halves2half2(l0, l1);
    *(__half2*)(row + 1024 + j + 2) = __halves2half2(l2, l3);
}

__global__ void dispatch_kernel(const float* __restrict__ x,
                                const float* __restrict__ shift,
                                const float* __restrict__ maak,
                                const float* __restrict__ maar) {
    const int slot = blockIdx.x;
    const int j = threadIdx.x * 4;
    __half* rk = g_dk_h + (size_t)slot * 2048;
    __half* rr = g_dr_h + (size_t)slot * 2048;
    const int tokidx = g_slot2tok[slot];
    float4 dk, dr;
    if (tokidx < 0) {
        dk = dr = make_float4(0.f, 0.f, 0.f, 0.f);
    } else {
        const int b = tokidx / Tt;
        const int t = tokidx % Tt;
        float4 xv = *(const float4*)&x[(size_t)tokidx * Mm + j];
        float4 xp;
        if (t == 0) xp = *(const float4*)&shift[(size_t)b * Mm + j];
        else        xp = *(const float4*)&x[(size_t)(tokidx - 1) * Mm + j];
        float4 mk = *(const float4*)&maak[j];
        float4 mr = *(const float4*)&maar[j];
        float4 dx = make_float4(xp.x - xv.x, xp.y - xv.y, xp.z - xv.z, xp.w - xv.w);
        dk = make_float4(fmaf(dx.x, mk.x, xv.x), fmaf(dx.y, mk.y, xv.y),
                         fmaf(dx.z, mk.z, xv.z), fmaf(dx.w, mk.w, xv.w));
        dr = make_float4(fmaf(dx.x, mr.x, xv.x), fmaf(dx.y, mr.y, xv.y),
                         fmaf(dx.z, mr.z, xv.z), fmaf(dx.w, mr.w, xv.w));
    }
    fp16_split4(rk, j, dk);
    fp16_split4(rr, j, dr);
}

// ---------------------------------------------------------------------------
// Weight transpose: W [E][K][N] fp32 -> W' [E][N][K] fp16 (hi only)
// ---------------------------------------------------------------------------
__global__ void wconv_fp16_kernel(const float* __restrict__ W,
                                  __half* __restrict__ out, int K, int N) {
    __shared__ float tile[32][33];
    const int e = blockIdx.z;
    const float* Wp = W + (size_t)e * K * N;
    __half* op = out + (size_t)e * N * K;
    const int k0 = blockIdx.y * 32, n0 = blockIdx.x * 32;
    const int tx = threadIdx.x, ty = threadIdx.y;
    #pragma unroll
    for (int i = 0; i < 32; i += 8)
        tile[ty + i][tx] = Wp[(size_t)(k0 + ty + i) * N + n0 + tx];
    __syncthreads();
    #pragma unroll
    for (int i = 0; i < 32; i += 8)
        op[(size_t)(n0 + ty + i) * K + k0 + tx] = __float2half(tile[tx][ty + i]);
}

// ---------------------------------------------------------------------------
// fp16 HMMA GEMM, 2-term A-split with B-fragment reuse:
// per kt load A_hi chunk + A_lo chunk + ONE B chunk; both term-MMAs share the
// B ldsm fragments.  Block 128x128, 256 thr, 8 warps (4M x 2N), warp 32x64.
// Stage = A_hi 8KB + A_lo 8KB + B 8KB = 24KB; 4 stages.
// EPI 0: relu^2 -> fp16 split [Hh|Hl]; EPI 1: f32 copy; EPI 2: sigmoid f32.
// ---------------------------------------------------------------------------
constexpr int STAGE_B   = 24576;
constexpr int GEMM_SMEM = 4 * STAGE_B;    // 96 KB

template<int EPI, int TCH>
__global__ void __launch_bounds__(256, 2)
gemm_mma(const __half* __restrict__ Ag, const __half* __restrict__ Bg,
         float* __restrict__ Cf, __half* __restrict__ Cb, int N) {
    constexpr int K      = TCH * 32;
    constexpr int AROW_B = 4 * K;     // [Ah|Al] row bytes
    constexpr int BROW_B = 2 * K;

    extern __shared__ __align__(1024) char smem[];
    const uint32_t sb = smem_u32(smem);
    const int tid = threadIdx.x;
    const int lane = tid & 31, warp = tid >> 5;
    const int wm = warp & 3, wn = warp >> 2;
    const int e = blockIdx.z;
    const int bm = blockIdx.y * 128, bn = blockIdx.x * 128;

    const char* Ahi = (const char*)Ag + ((size_t)e * 2048 + bm) * AROW_B;
    const char* Alo = Ahi + 2 * K;                      // bytes
    const char* B   = (const char*)Bg + ((size_t)e * N + bn) * BROW_B;

    // loader: 256 threads; each region 128 rows x 64B; 2 rows/thread/region
    const int lr = tid >> 2, lc = tid & 3;
    const uint32_t sw0 = (uint32_t)(lr * 64 + ((lc ^ ((lr >> 1) & 3)) << 4));
    const uint32_t sw1 = (uint32_t)((lr + 64) * 64 + ((lc ^ (((lr + 64) >> 1) & 3)) << 4));
    const uint32_t cbL = (uint32_t)(lc * 16);

    auto load_stage = [&](int st, int kt) {
        const int colB = kt * 64;
        const uint32_t b = sb + st * STAGE_B;
        cp16(b + sw0,         Ahi + (size_t)lr * AROW_B + colB + cbL);
        cp16(b + sw1,         Ahi + (size_t)(lr + 64) * AROW_B + colB + cbL);
        cp16(b + 8192 + sw0,  Alo + (size_t)lr * AROW_B + colB + cbL);
        cp16(b + 8192 + sw1,  Alo + (size_t)(lr + 64) * AROW_B + colB + cbL);
        cp16(b + 16384 + sw0, B + (size_t)lr * BROW_B + colB + cbL);
        cp16(b + 16384 + sw1, B + (size_t)(lr + 64) * BROW_B + colB + cbL);
    };

    // ldmatrix offsets: warp tile 32 rows (2 m16 frags) x 64 cols (4 n16 frags)
    const int rowA0 = wm * 32 + (lane & 15);
    const uint32_t aOff = (uint32_t)(rowA0 * 64 +
                          (((lane >> 4) ^ ((rowA0 >> 1) & 3)) << 4));
    const int rowB0 = wn * 64 + (lane & 7) + ((lane >> 4) << 3);
    const uint32_t bOff = (uint32_t)(rowB0 * 64 +
                          ((((lane >> 3) & 1) ^ ((rowB0 >> 1) & 3)) << 4));

    float acc[2][8][4];
    #pragma unroll
    for (int i = 0; i < 2; ++i)
        #pragma unroll
        for (int j = 0; j < 8; ++j)
            #pragma unroll
            for (int k = 0; k < 4; ++k) acc[i][j][k] = 0.f;

    load_stage(0, 0); CP_COMMIT();
    load_stage(1, 1); CP_COMMIT();
    load_stage(2, 2); CP_COMMIT();

    for (int kt = 0; kt < TCH; ++kt) {
        CP_WAIT2();
        __syncthreads();
        if (kt + 3 < TCH) load_stage((kt + 3) & 3, kt + 3);
        CP_COMMIT();

        const uint32_t stb = sb + (kt & 3) * STAGE_B;
        #pragma unroll
        for (int ks = 0; ks < 2; ++ks) {
            const uint32_t kx = ks * 32;
            uint32_t ah[2][4], al[2][4];
            #pragma unroll
            for (int mi = 0; mi < 2; ++mi) {
                LDSM_X4(ah[mi], (stb + aOff + mi * 1024) ^ kx);
                LDSM_X4(al[mi], (stb + 8192 + aOff + mi * 1024) ^ kx);
            }
            uint32_t b[4][4];
            #pragma unroll
            for (int nf2 = 0; nf2 < 4; ++nf2)
                LDSM_X4(b[nf2], (stb + 16384 + bOff + nf2 * 1024) ^ kx);
            #pragma unroll
            for (int mi = 0; mi < 2; ++mi)
                #pragma unroll
                for (int nf2 = 0; nf2 < 4; ++nf2) {
                    mma_fp16(acc[mi][nf2 * 2 + 0], ah[mi], b[nf2][0], b[nf2][1]);
                    mma_fp16(acc[mi][nf2 * 2 + 1], ah[mi], b[nf2][2], b[nf2][3]);
                    mma_fp16(acc[mi][nf2 * 2 + 0], al[mi], b[nf2][0], b[nf2][1]);
                    mma_fp16(acc[mi][nf2 * 2 + 1], al[mi], b[nf2][2], b[nf2][3]);
                }
        }
    }

    // Epilogue
    #pragma unroll
    for (int mi = 0; mi < 2; ++mi) {
        #pragma unroll
        for (int nf = 0; nf < 8; ++nf) {
            const float* c = acc[mi][nf];
            const int col = bn + wn * 64 + nf * 8 + (lane & 3) * 2;
            const int row0 = bm + wm * 32 + mi * 16 + (lane >> 2);
            #pragma unroll
            for (int hh = 0; hh < 2; ++hh) {
                const int row = row0 + hh * 8;
                float v0 = c[hh * 2 + 0], v1 = c[hh * 2 + 1];
                if (EPI == 0) {
                    v0 = v0 > 0.f ? v0 * v0 : 0.f;
                    v1 = v1 > 0.f ? v1 * v1 : 0.f;
                    __half h0 = __float2half(v0);
                    __half h1 = __float2half(v1);
                    __half l0 = __float2half(v0 - __half2float(h0));
                    __half l1 = __float2half(v1 - __half2float(h1));
                    __half* p = Cb + ((size_t)e * 2048 + row) * (size_t)(2 * N) + col;
                    *(__half2*)p       = __halves2half2(h0, h1);
                    *(__half2*)(p + N) = __halves2half2(l0, l1);
                } else {
                    if (EPI == 2) {
                        v0 = 1.f / (1.f + __expf(-v0));
                        v1 = 1.f / (1.f + __expf(-v1));
                    }
                    float* p = Cf + ((size_t)e * 2048 + row) * (size_t)N + col;
                    *(float2*)p = make_float2(v0, v1);
                }
            }
        }
    }
}

// ---------------------------------------------------------------------------
// Combine + shift
// ---------------------------------------------------------------------------
__global__ void combine_kernel(float* __restrict__ out) {
    const int s = blockIdx.x;
    const int j = threadIdx.x * 4;
    const size_t oo = (size_t)s * Mm + j;
    const int slot = g_tok2slot[s];
    float4 o = make_float4(0.f, 0.f, 0.f, 0.f);
    if (slot < ECAP) {
        const size_t so = (size_t)slot * Mm + j;
        float4 rv = *(const float4*)&g_r[so];
        float4 kv = *(const float4*)&g_kv[so];
        o = make_float4(rv.x * kv.x, rv.y * kv.y, rv.z * kv.z, rv.w * kv.w);
    }
    *(float4*)&out[oo] = o;
}
__global__ void shift_kernel(const float* __restrict__ x, float* __restrict__ out) {
    const int b = blockIdx.x;
    const int j = threadIdx.x * 4;
    *(float4*)&out[(size_t)Ss * Mm + (size_t)b * Mm + j] =
        *(const float4*)&x[((size_t)b * Tt + (Tt - 1)) * Mm + j];
}

// ---------------------------------------------------------------------------
// Host
// ---------------------------------------------------------------------------
extern "C" void kernel_launch(void* const* d_in, const int* in_sizes, int n_in,
                              void* d_out, int out_size) {
    const float* x     = (const float*)d_in[0];
    const int*   tok   = (const int*)  d_in[1];
    const float* shift = (const float*)d_in[2];
    const float* maak  = (const float*)d_in[3];
    const float* maar  = (const float*)d_in[4];
    const float* Wk    = (const float*)d_in[5];
    const float* Wv    = (const float*)d_in[6];
    const float* Wr    = (const float*)d_in[7];
    float* out = (float*)d_out;

    void *dkh, *drh, *hh, *wkh, *wvh, *wrh, *kvp, *rp;
    cudaGetSymbolAddress(&dkh, g_dk_h);
    cudaGetSymbolAddress(&drh, g_dr_h);
    cudaGetSymbolAddress(&hh,  g_h_h);
    cudaGetSymbolAddress(&wkh, g_Wk_h);
    cudaGetSymbolAddress(&wvh, g_Wv_h);
    cudaGetSymbolAddress(&wrh, g_Wr_h);
    cudaGetSymbolAddress(&kvp, g_kv);
    cudaGetSymbolAddress(&rp,  g_r);

    cudaFuncSetAttribute((const void*)gemm_mma<0, 32>,
                         cudaFuncAttributeMaxDynamicSharedMemorySize, GEMM_SMEM);
    cudaFuncSetAttribute((const void*)gemm_mma<1, 64>,
                         cudaFuncAttributeMaxDynamicSharedMemorySize, GEMM_SMEM);
    cudaFuncSetAttribute((const void*)gemm_mma<2, 32>,
                         cudaFuncAttributeMaxDynamicSharedMemorySize, GEMM_SMEM);

    route_kernel<<<1, 256>>>(tok);
    dispatch_kernel<<<ECAP, 256>>>(x, shift, maak, maar);
    wconv_fp16_kernel<<<dim3(64, 32, 8), dim3(32, 8)>>>(Wk, (__half*)wkh, 1024, 2048);
    wconv_fp16_kernel<<<dim3(32, 64, 8), dim3(32, 8)>>>(Wv, (__half*)wvh, 2048, 1024);
    wconv_fp16_kernel<<<dim3(32, 32, 8), dim3(32, 8)>>>(Wr, (__half*)wrh, 1024, 1024);

    // h = relu^2(dk @ Wk): K=1024, 32 kt iters; writes fp16 [Hh|Hl]
    gemm_mma<0, 32><<<dim3(16, 16, 8), 256, GEMM_SMEM>>>(
        (const __half*)dkh, (const __half*)wkh, nullptr, (__half*)hh, 2048);
    // kv = h @ Wv: K=2048, 64 kt iters
    gemm_mma<1, 64><<<dim3(8, 16, 8), 256, GEMM_SMEM>>>(
        (const __half*)hh, (const __half*)wvh, (float*)kvp, nullptr, 1024);
    // r = sigmoid(dr @ Wr): K=1024, 32 kt iters
    gemm_mma<2, 32><<<dim3(8, 16, 8), 256, GEMM_SMEM>>>(
        (const __half*)drh, (const __half*)wrh, (float*)rp, nullptr, 1024);

    combine_kernel<<<Ss, 256>>>(out);
    if ((size_t)out_size >= (size_t)Ss * Mm + (size_t)Bb * Mm)
        shift_kernel<<<Bb, 256>>>(x, out);
}

// round 8
// speedup vs baseline: 5.0858x; 1.1730x over previous
#include <cuda_runtime.h>
#include <cuda_fp16.h>
#include <stdint.h>

// ---------------------------------------------------------------------------
// Problem constants
// ---------------------------------------------------------------------------
#define Bb 8
#define Tt 2048
#define Mm 1024
#define Ff 2048
#define Ee 8
#define Ss 16384
#define CAP 2048
#define ECAP 16384
#define DROPPED 0x7FFFFFFF

// fp16 precision tiers:
//  dk, dr : fp16 [ECAP][2048] = [Ah|Al]   (2-term, ~2^-22 exact)
//  h      : fp16 [ECAP][2048] hi only     (GEMM2 single-term)
//  Wk',Wv',Wr' : fp16 hi only, N-major
__device__ __align__(128) __half g_dk_h[(size_t)ECAP * 2048];
__device__ __align__(128) __half g_dr_h[(size_t)ECAP * 2048];
__device__ __align__(128) __half g_h_h [(size_t)ECAP * 2048];
__device__ __align__(128) __half g_Wk_h[(size_t)Ee * 2048 * 1024];
__device__ __align__(128) __half g_Wv_h[(size_t)Ee * 1024 * 2048];
__device__ __align__(128) __half g_Wr_h[(size_t)Ee * 1024 * 1024];
__device__ float g_kv[(size_t)ECAP * Mm];
__device__ int   g_slot2tok[ECAP];
__device__ int   g_tok2slot[Ss];

// ---------------------------------------------------------------------------
// PTX helpers
// ---------------------------------------------------------------------------
__device__ __forceinline__ uint32_t smem_u32(const void* p) {
    uint32_t a;
    asm("{ .reg .u64 t; cvta.to.shared.u64 t, %1; cvt.u32.u64 %0, t; }" : "=r"(a) : "l"(p));
    return a;
}
__device__ __forceinline__ void cp16(uint32_t s, const void* g) {
    asm volatile("cp.async.cg.shared.global [%0], [%1], 16;" :: "r"(s), "l"(g) : "memory");
}
#define CP_COMMIT() asm volatile("cp.async.commit_group;" ::: "memory")
#define CP_WAIT2()  asm volatile("cp.async.wait_group 2;" ::: "memory")

#define LDSM_X4(r, a) \
    asm volatile("ldmatrix.sync.aligned.m8n8.x4.shared.b16 {%0,%1,%2,%3}, [%4];" \
        : "=r"((r)[0]), "=r"((r)[1]), "=r"((r)[2]), "=r"((r)[3]) : "r"(a))

__device__ __forceinline__ void mma_fp16(float* c, const uint32_t* a,
                                         uint32_t b0, uint32_t b1) {
    asm volatile(
        "mma.sync.aligned.m16n8k16.row.col.f32.f16.f16.f32 "
        "{%0,%1,%2,%3}, {%4,%5,%6,%7}, {%8,%9}, {%0,%1,%2,%3};"
        : "+f"(c[0]), "+f"(c[1]), "+f"(c[2]), "+f"(c[3])
        : "r"(a[0]), "r"(a[1]), "r"(a[2]), "r"(a[3]), "r"(b0), "r"(b1));
}

// ---------------------------------------------------------------------------
// Routing
// ---------------------------------------------------------------------------
__global__ void route_kernel(const int* __restrict__ tok) {
    __shared__ int cnt[256][8];
    const int t = threadIdx.x;
    for (int i = t; i < ECAP; i += 256) g_slot2tok[i] = -1;
    const int base = t * 64;
    int c[8] = {0,0,0,0,0,0,0,0};
    for (int i = 0; i < 64; ++i) { int e = (tok[base + i] * 5099) & 7; c[e]++; }
    #pragma unroll
    for (int e = 0; e < 8; ++e) cnt[t][e] = c[e];
    __syncthreads();
    if (t < 8) {
        int run = 0;
        for (int j = 0; j < 256; ++j) { int v = cnt[j][t]; cnt[j][t] = run; run += v; }
    }
    __syncthreads();
    int run[8];
    #pragma unroll
    for (int e = 0; e < 8; ++e) run[e] = cnt[t][e];
    for (int i = 0; i < 64; ++i) {
        int s = base + i;
        int e = (tok[s] * 5099) & 7;
        int pos = run[e]++;
        if (pos < CAP) { int slot = e * CAP + pos; g_tok2slot[s] = slot; g_slot2tok[slot] = s; }
        else g_tok2slot[s] = DROPPED;
    }
}

// ---------------------------------------------------------------------------
// Dispatch: token-shift mix; dk & dr as fp16 [Ah|Al]
// ---------------------------------------------------------------------------
__device__ __forceinline__ void fp16_split4(__half* row, int j, float4 v) {
    __half h0 = __float2half(v.x), h1 = __float2half(v.y);
    __half h2 = __float2half(v.z), h3 = __float2half(v.w);
    __half l0 = __float2half(v.x - __half2float(h0));
    __half l1 = __float2half(v.y - __half2float(h1));
    __half l2 = __float2half(v.z - __half2float(h2));
    __half l3 = __float2half(v.w - __half2float(h3));
    *(__half2*)(row + j)            = __halves2half2(h0, h1);
    *(__half2*)(row + j + 2)        = __halves2half2(h2, h3);
    *(__half2*)(row + 1024 + j)     = __halves2half2(l0, l1);
    *(__half2*)(row + 1024 + j + 2) = __halves2half2(l2, l3);
}

__global__ void dispatch_kernel(const float* __restrict__ x,
                                const float* __restrict__ shift,
                                const float* __restrict__ maak,
                                const float* __restrict__ maar) {
    const int slot = blockIdx.x;
    const int j = threadIdx.x * 4;
    __half* rk = g_dk_h + (size_t)slot * 2048;
    __half* rr = g_dr_h + (size_t)slot * 2048;
    const int tokidx = g_slot2tok[slot];
    float4 dk, dr;
    if (tokidx < 0) {
        dk = dr = make_float4(0.f, 0.f, 0.f, 0.f);
    } else {
        const int b = tokidx / Tt;
        const int t = tokidx % Tt;
        float4 xv = *(const float4*)&x[(size_t)tokidx * Mm + j];
        float4 xp;
        if (t == 0) xp = *(const float4*)&shift[(size_t)b * Mm + j];
        else        xp = *(const float4*)&x[(size_t)(tokidx - 1) * Mm + j];
        float4 mk = *(const float4*)&maak[j];
        float4 mr = *(const float4*)&maar[j];
        float4 dx = make_float4(xp.x - xv.x, xp.y - xv.y, xp.z - xv.z, xp.w - xv.w);
        dk = make_float4(fmaf(dx.x, mk.x, xv.x), fmaf(dx.y, mk.y, xv.y),
                         fmaf(dx.z, mk.z, xv.z), fmaf(dx.w, mk.w, xv.w));
        dr = make_float4(fmaf(dx.x, mr.x, xv.x), fmaf(dx.y, mr.y, xv.y),
                         fmaf(dx.z, mr.z, xv.z), fmaf(dx.w, mr.w, xv.w));
    }
    fp16_split4(rk, j, dk);
    fp16_split4(rr, j, dr);
}

// ---------------------------------------------------------------------------
// Weight transpose: W [E][K][N] fp32 -> W' [E][N][K] fp16 (hi only)
// ---------------------------------------------------------------------------
__global__ void wconv_fp16_kernel(const float* __restrict__ W,
                                  __half* __restrict__ out, int K, int N) {
    __shared__ float tile[32][33];
    const int e = blockIdx.z;
    const float* Wp = W + (size_t)e * K * N;
    __half* op = out + (size_t)e * N * K;
    const int k0 = blockIdx.y * 32, n0 = blockIdx.x * 32;
    const int tx = threadIdx.x, ty = threadIdx.y;
    #pragma unroll
    for (int i = 0; i < 32; i += 8)
        tile[ty + i][tx] = Wp[(size_t)(k0 + ty + i) * N + n0 + tx];
    __syncthreads();
    #pragma unroll
    for (int i = 0; i < 32; i += 8)
        op[(size_t)(n0 + ty + i) * K + k0 + tx] = __float2half(tile[tx][ty + i]);
}

// ---------------------------------------------------------------------------
// fp16 HMMA GEMM. TERMS=2: A=[Ah|Al], B shared across both term-MMAs.
// TERMS=1: plain fp16 GEMM. Block 128x128, 256 thr, 8 warps (4M x 2N).
// Stage layout: [Ah 8KB][Al 8KB iff TERMS==2][B 8KB]  => STAGE=(TERMS+1)*8KB
// EPI 0: relu^2 -> fp16 hi into Cb. EPI 1: f32 copy to Cf.
// EPI 3: sigmoid * kv[slot] scattered to out[token] (fused combine).
// ---------------------------------------------------------------------------
template<int EPI, int TCH, int TERMS>
__global__ void __launch_bounds__(256, 2)
gemm_mma(const __half* __restrict__ Ag, const __half* __restrict__ Bg,
         float* __restrict__ Cf, __half* __restrict__ Cb,
         const float* __restrict__ KV, int N) {
    constexpr int K      = TCH * 32;
    constexpr int AROW_B = 2 * TERMS * K;
    constexpr int BROW_B = 2 * K;
    constexpr int STAGE  = (TERMS + 1) * 8192;   // FIXED: 24KB (2-term) / 16KB (1-term)
    constexpr int BOFF   = TERMS * 8192;

    extern __shared__ __align__(1024) char smem[];
    const uint32_t sb = smem_u32(smem);
    const int tid = threadIdx.x;
    const int lane = tid & 31, warp = tid >> 5;
    const int wm = warp & 3, wn = warp >> 2;
    const int e = blockIdx.z;
    const int bm = blockIdx.y * 128, bn = blockIdx.x * 128;

    const char* Ahi = (const char*)Ag + ((size_t)e * 2048 + bm) * AROW_B;
    const char* Alo = Ahi + 2 * K;
    const char* B   = (const char*)Bg + ((size_t)e * N + bn) * BROW_B;

    const int lr = tid >> 2, lc = tid & 3;
    const uint32_t sw0 = (uint32_t)(lr * 64 + ((lc ^ ((lr >> 1) & 3)) << 4));
    const uint32_t sw1 = (uint32_t)((lr + 64) * 64 + ((lc ^ (((lr + 64) >> 1) & 3)) << 4));
    const uint32_t cbL = (uint32_t)(lc * 16);

    auto load_stage = [&](int st, int kt) {
        const int colB = kt * 64;
        const uint32_t b = sb + st * STAGE;
        cp16(b + sw0, Ahi + (size_t)lr * AROW_B + colB + cbL);
        cp16(b + sw1, Ahi + (size_t)(lr + 64) * AROW_B + colB + cbL);
        if (TERMS == 2) {
            cp16(b + 8192 + sw0, Alo + (size_t)lr * AROW_B + colB + cbL);
            cp16(b + 8192 + sw1, Alo + (size_t)(lr + 64) * AROW_B + colB + cbL);
        }
        cp16(b + BOFF + sw0, B + (size_t)lr * BROW_B + colB + cbL);
        cp16(b + BOFF + sw1, B + (size_t)(lr + 64) * BROW_B + colB + cbL);
    };

    const int rowA0 = wm * 32 + (lane & 15);
    const uint32_t aOff = (uint32_t)(rowA0 * 64 +
                          (((lane >> 4) ^ ((rowA0 >> 1) & 3)) << 4));
    const int rowB0 = wn * 64 + (lane & 7) + ((lane >> 4) << 3);
    const uint32_t bOff = (uint32_t)(rowB0 * 64 +
                          ((((lane >> 3) & 1) ^ ((rowB0 >> 1) & 3)) << 4));

    float acc[2][8][4];
    #pragma unroll
    for (int i = 0; i < 2; ++i)
        #pragma unroll
        for (int j = 0; j < 8; ++j)
            #pragma unroll
            for (int k = 0; k < 4; ++k) acc[i][j][k] = 0.f;

    load_stage(0, 0); CP_COMMIT();
    load_stage(1, 1); CP_COMMIT();
    load_stage(2, 2); CP_COMMIT();

    for (int kt = 0; kt < TCH; ++kt) {
        CP_WAIT2();
        __syncthreads();
        if (kt + 3 < TCH) load_stage((kt + 3) & 3, kt + 3);
        CP_COMMIT();

        const uint32_t stb = sb + (kt & 3) * STAGE;
        #pragma unroll
        for (int ks = 0; ks < 2; ++ks) {
            const uint32_t kx = ks * 32;
            uint32_t ah[2][4], al[2][4];
            #pragma unroll
            for (int mi = 0; mi < 2; ++mi) {
                LDSM_X4(ah[mi], (stb + aOff + mi * 1024) ^ kx);
                if (TERMS == 2) LDSM_X4(al[mi], (stb + 8192 + aOff + mi * 1024) ^ kx);
            }
            uint32_t b[4][4];
            #pragma unroll
            for (int nf2 = 0; nf2 < 4; ++nf2)
                LDSM_X4(b[nf2], (stb + BOFF + bOff + nf2 * 1024) ^ kx);
            #pragma unroll
            for (int mi = 0; mi < 2; ++mi)
                #pragma unroll
                for (int nf2 = 0; nf2 < 4; ++nf2) {
                    mma_fp16(acc[mi][nf2 * 2 + 0], ah[mi], b[nf2][0], b[nf2][1]);
                    mma_fp16(acc[mi][nf2 * 2 + 1], ah[mi], b[nf2][2], b[nf2][3]);
                    if (TERMS == 2) {
                        mma_fp16(acc[mi][nf2 * 2 + 0], al[mi], b[nf2][0], b[nf2][1]);
                        mma_fp16(acc[mi][nf2 * 2 + 1], al[mi], b[nf2][2], b[nf2][3]);
                    }
                }
        }
    }

    // Epilogue
    #pragma unroll
    for (int mi = 0; mi < 2; ++mi) {
        #pragma unroll
        for (int nf = 0; nf < 8; ++nf) {
            const float* c = acc[mi][nf];
            const int col = bn + wn * 64 + nf * 8 + (lane & 3) * 2;
            const int row0 = bm + wm * 32 + mi * 16 + (lane >> 2);
            #pragma unroll
            for (int hh = 0; hh < 2; ++hh) {
                const int row = row0 + hh * 8;
                float v0 = c[hh * 2 + 0], v1 = c[hh * 2 + 1];
                if (EPI == 0) {
                    v0 = v0 > 0.f ? v0 * v0 : 0.f;
                    v1 = v1 > 0.f ? v1 * v1 : 0.f;
                    __half* p = Cb + ((size_t)e * 2048 + row) * (size_t)N + col;
                    *(__half2*)p = __halves2half2(__float2half(v0), __float2half(v1));
                } else if (EPI == 1) {
                    float* p = Cf + ((size_t)e * 2048 + row) * (size_t)N + col;
                    *(float2*)p = make_float2(v0, v1);
                } else {   // EPI == 3: fused sigmoid * kv -> out[token]
                    const int slot = e * 2048 + row;
                    const int tokidx = g_slot2tok[slot];
                    if (tokidx >= 0) {
                        float2 kv = *(const float2*)&KV[(size_t)slot * N + col];
                        v0 = kv.x / (1.f + __expf(-v0));
                        v1 = kv.y / (1.f + __expf(-v1));
                        *(float2*)&Cf[(size_t)tokidx * N + col] = make_float2(v0, v1);
                    }
                }
            }
        }
    }
}

// ---------------------------------------------------------------------------
// Zero-fill for dropped tokens; shift state
// ---------------------------------------------------------------------------
__global__ void zero_dropped_kernel(float* __restrict__ out) {
    const int s = blockIdx.x;
    if (g_tok2slot[s] != DROPPED) return;
    const int j = threadIdx.x * 4;
    *(float4*)&out[(size_t)s * Mm + j] = make_float4(0.f, 0.f, 0.f, 0.f);
}
__global__ void shift_kernel(const float* __restrict__ x, float* __restrict__ out) {
    const int b = blockIdx.x;
    const int j = threadIdx.x * 4;
    *(float4*)&out[(size_t)Ss * Mm + (size_t)b * Mm + j] =
        *(const float4*)&x[((size_t)b * Tt + (Tt - 1)) * Mm + j];
}

// ---------------------------------------------------------------------------
// Host
// ---------------------------------------------------------------------------
extern "C" void kernel_launch(void* const* d_in, const int* in_sizes, int n_in,
                              void* d_out, int out_size) {
    const float* x     = (const float*)d_in[0];
    const int*   tok   = (const int*)  d_in[1];
    const float* shift = (const float*)d_in[2];
    const float* maak  = (const float*)d_in[3];
    const float* maar  = (const float*)d_in[4];
    const float* Wk    = (const float*)d_in[5];
    const float* Wv    = (const float*)d_in[6];
    const float* Wr    = (const float*)d_in[7];
    float* out = (float*)d_out;

    void *dkh, *drh, *hh, *wkh, *wvh, *wrh, *kvp;
    cudaGetSymbolAddress(&dkh, g_dk_h);
    cudaGetSymbolAddress(&drh, g_dr_h);
    cudaGetSymbolAddress(&hh,  g_h_h);
    cudaGetSymbolAddress(&wkh, g_Wk_h);
    cudaGetSymbolAddress(&wvh, g_Wv_h);
    cudaGetSymbolAddress(&wrh, g_Wr_h);
    cudaGetSymbolAddress(&kvp, g_kv);

    constexpr int SM1 = 4 * 24576;   // TERMS=2: 4 stages x 24KB
    constexpr int SM2 = 4 * 16384;   // TERMS=1: 4 stages x 16KB
    cudaFuncSetAttribute((const void*)gemm_mma<0, 32, 2>,
                         cudaFuncAttributeMaxDynamicSharedMemorySize, SM1);
    cudaFuncSetAttribute((const void*)gemm_mma<1, 64, 1>,
                         cudaFuncAttributeMaxDynamicSharedMemorySize, SM2);
    cudaFuncSetAttribute((const void*)gemm_mma<3, 32, 2>,
                         cudaFuncAttributeMaxDynamicSharedMemorySize, SM1);

    route_kernel<<<1, 256>>>(tok);
    dispatch_kernel<<<ECAP, 256>>>(x, shift, maak, maar);
    wconv_fp16_kernel<<<dim3(64, 32, 8), dim3(32, 8)>>>(Wk, (__half*)wkh, 1024, 2048);
    wconv_fp16_kernel<<<dim3(32, 64, 8), dim3(32, 8)>>>(Wv, (__half*)wvh, 2048, 1024);
    wconv_fp16_kernel<<<dim3(32, 32, 8), dim3(32, 8)>>>(Wr, (__half*)wrh, 1024, 1024);

    // h = relu^2(dk @ Wk): 2-term, K=1024; writes fp16 hi only
    gemm_mma<0, 32, 2><<<dim3(16, 16, 8), 256, SM1>>>(
        (const __half*)dkh, (const __half*)wkh, nullptr, (__half*)hh, nullptr, 2048);
    // kv = h @ Wv: single-term fp16, K=2048
    gemm_mma<1, 64, 1><<<dim3(8, 16, 8), 256, SM2>>>(
        (const __half*)hh, (const __half*)wvh, (float*)kvp, nullptr, nullptr, 1024);
    // out[token] = sigmoid(dr @ Wr) * kv  (fused combine): 2-term, K=1024
    gemm_mma<3, 32, 2><<<dim3(8, 16, 8), 256, SM1>>>(
        (const __half*)drh, (const __half*)wrh, out, nullptr,
        (const float*)kvp, 1024);

    zero_dropped_kernel<<<Ss, 256>>>(out);
    if ((size_t)out_size >= (size_t)Ss * Mm + (size_t)Bb * Mm)
        shift_kernel<<<Bb, 256>>>(x, out);
}

// round 9
// speedup vs baseline: 5.5456x; 1.0904x over previous
#include <cuda_runtime.h>
#include <cuda_fp16.h>
#include <stdint.h>

// ---------------------------------------------------------------------------
// Problem constants
// ---------------------------------------------------------------------------
#define Bb 8
#define Tt 2048
#define Mm 1024
#define Ff 2048
#define Ee 8
#define Ss 16384
#define CAP 2048
#define ECAP 16384
#define DROPPED 0x7FFFFFFF

// fp16 precision tiers:
//  dk : fp16 [ECAP][2048] = [Ah|Al]  (2-term — relu^2 amplifies error)
//  dr : fp16 [ECAP][1024] hi only    (single-term — sigmoid damps error)
//  h  : fp16 [ECAP][2048] hi only    (single-term)
//  Wk',Wv',Wr' : fp16 hi only, N-major
__device__ __align__(128) __half g_dk_h[(size_t)ECAP * 2048];
__device__ __align__(128) __half g_dr_h[(size_t)ECAP * 1024];
__device__ __align__(128) __half g_h_h [(size_t)ECAP * 2048];
__device__ __align__(128) __half g_Wk_h[(size_t)Ee * 2048 * 1024];
__device__ __align__(128) __half g_Wv_h[(size_t)Ee * 1024 * 2048];
__device__ __align__(128) __half g_Wr_h[(size_t)Ee * 1024 * 1024];
__device__ float g_kv[(size_t)ECAP * Mm];
__device__ int   g_slot2tok[ECAP];
__device__ int   g_tok2slot[Ss];

// ---------------------------------------------------------------------------
// PTX helpers
// ---------------------------------------------------------------------------
__device__ __forceinline__ uint32_t smem_u32(const void* p) {
    uint32_t a;
    asm("{ .reg .u64 t; cvta.to.shared.u64 t, %1; cvt.u32.u64 %0, t; }" : "=r"(a) : "l"(p));
    return a;
}
__device__ __forceinline__ void cp16(uint32_t s, const void* g) {
    asm volatile("cp.async.cg.shared.global [%0], [%1], 16;" :: "r"(s), "l"(g) : "memory");
}
#define CP_COMMIT() asm volatile("cp.async.commit_group;" ::: "memory")
#define CP_WAIT2()  asm volatile("cp.async.wait_group 2;" ::: "memory")

#define LDSM_X4(r, a) \
    asm volatile("ldmatrix.sync.aligned.m8n8.x4.shared.b16 {%0,%1,%2,%3}, [%4];" \
        : "=r"((r)[0]), "=r"((r)[1]), "=r"((r)[2]), "=r"((r)[3]) : "r"(a))

__device__ __forceinline__ void mma_fp16(float* c, const uint32_t* a,
                                         uint32_t b0, uint32_t b1) {
    asm volatile(
        "mma.sync.aligned.m16n8k16.row.col.f32.f16.f16.f32 "
        "{%0,%1,%2,%3}, {%4,%5,%6,%7}, {%8,%9}, {%0,%1,%2,%3};"
        : "+f"(c[0]), "+f"(c[1]), "+f"(c[2]), "+f"(c[3])
        : "r"(a[0]), "r"(a[1]), "r"(a[2]), "r"(a[3]), "r"(b0), "r"(b1));
}

// ---------------------------------------------------------------------------
// Routing
// ---------------------------------------------------------------------------
__global__ void route_kernel(const int* __restrict__ tok) {
    __shared__ int cnt[256][8];
    const int t = threadIdx.x;
    for (int i = t; i < ECAP; i += 256) g_slot2tok[i] = -1;
    const int base = t * 64;
    int c[8] = {0,0,0,0,0,0,0,0};
    for (int i = 0; i < 64; ++i) { int e = (tok[base + i] * 5099) & 7; c[e]++; }
    #pragma unroll
    for (int e = 0; e < 8; ++e) cnt[t][e] = c[e];
    __syncthreads();
    if (t < 8) {
        int run = 0;
        for (int j = 0; j < 256; ++j) { int v = cnt[j][t]; cnt[j][t] = run; run += v; }
    }
    __syncthreads();
    int run[8];
    #pragma unroll
    for (int e = 0; e < 8; ++e) run[e] = cnt[t][e];
    for (int i = 0; i < 64; ++i) {
        int s = base + i;
        int e = (tok[s] * 5099) & 7;
        int pos = run[e]++;
        if (pos < CAP) { int slot = e * CAP + pos; g_tok2slot[s] = slot; g_slot2tok[slot] = s; }
        else g_tok2slot[s] = DROPPED;
    }
}

// ---------------------------------------------------------------------------
// Dispatch: token-shift mix; dk fp16 [Ah|Al], dr fp16 hi only
// ---------------------------------------------------------------------------
__global__ void dispatch_kernel(const float* __restrict__ x,
                                const float* __restrict__ shift,
                                const float* __restrict__ maak,
                                const float* __restrict__ maar) {
    const int slot = blockIdx.x;
    const int j = threadIdx.x * 4;
    __half* rk = g_dk_h + (size_t)slot * 2048;
    __half* rr = g_dr_h + (size_t)slot * 1024;
    const int tokidx = g_slot2tok[slot];
    float4 dk, dr;
    if (tokidx < 0) {
        dk = dr = make_float4(0.f, 0.f, 0.f, 0.f);
    } else {
        const int b = tokidx / Tt;
        const int t = tokidx % Tt;
        float4 xv = *(const float4*)&x[(size_t)tokidx * Mm + j];
        float4 xp;
        if (t == 0) xp = *(const float4*)&shift[(size_t)b * Mm + j];
        else        xp = *(const float4*)&x[(size_t)(tokidx - 1) * Mm + j];
        float4 mk = *(const float4*)&maak[j];
        float4 mr = *(const float4*)&maar[j];
        float4 dx = make_float4(xp.x - xv.x, xp.y - xv.y, xp.z - xv.z, xp.w - xv.w);
        dk = make_float4(fmaf(dx.x, mk.x, xv.x), fmaf(dx.y, mk.y, xv.y),
                         fmaf(dx.z, mk.z, xv.z), fmaf(dx.w, mk.w, xv.w));
        dr = make_float4(fmaf(dx.x, mr.x, xv.x), fmaf(dx.y, mr.y, xv.y),
                         fmaf(dx.z, mr.z, xv.z), fmaf(dx.w, mr.w, xv.w));
    }
    // dk: 2-term split
    {
        __half h0 = __float2half(dk.x), h1 = __float2half(dk.y);
        __half h2 = __float2half(dk.z), h3 = __float2half(dk.w);
        __half l0 = __float2half(dk.x - __half2float(h0));
        __half l1 = __float2half(dk.y - __half2float(h1));
        __half l2 = __float2half(dk.z - __half2float(h2));
        __half l3 = __float2half(dk.w - __half2float(h3));
        *(__half2*)(rk + j)            = __halves2half2(h0, h1);
        *(__half2*)(rk + j + 2)        = __halves2half2(h2, h3);
        *(__half2*)(rk + 1024 + j)     = __halves2half2(l0, l1);
        *(__half2*)(rk + 1024 + j + 2) = __halves2half2(l2, l3);
    }
    // dr: hi only
    {
        *(__half2*)(rr + j)     = __halves2half2(__float2half(dr.x), __float2half(dr.y));
        *(__half2*)(rr + j + 2) = __halves2half2(__float2half(dr.z), __float2half(dr.w));
    }
}

// ---------------------------------------------------------------------------
// Weight transpose: W [E][K][N] fp32 -> W' [E][N][K] fp16 (hi only)
// 64k x 32n tile; writes vectorized __half2 so each warp stores 128B lines.
// ---------------------------------------------------------------------------
__global__ void wconv_fp16_kernel(const float* __restrict__ W,
                                  __half* __restrict__ out, int K, int N) {
    __shared__ __half tile[64][33];
    const int e = blockIdx.z;
    const float* Wp = W + (size_t)e * K * N;
    __half* op = out + (size_t)e * N * K;
    const int k0 = blockIdx.y * 64, n0 = blockIdx.x * 32;
    const int tx = threadIdx.x, ty = threadIdx.y;   // (32, 8)
    #pragma unroll
    for (int i = 0; i < 8; ++i)
        tile[ty + i * 8][tx] = __float2half(Wp[(size_t)(k0 + ty + i * 8) * N + n0 + tx]);
    __syncthreads();
    #pragma unroll
    for (int j = 0; j < 4; ++j) {
        const int n = ty + j * 8;
        __half2 v = __halves2half2(tile[tx * 2][n], tile[tx * 2 + 1][n]);
        *(__half2*)&op[(size_t)(n0 + n) * K + k0 + tx * 2] = v;
    }
}

// ---------------------------------------------------------------------------
// fp16 HMMA GEMM. TERMS=2: A=[Ah|Al], B shared across both term-MMAs.
// TERMS=1: plain fp16 GEMM. Block 128x128, 256 thr, 8 warps (4M x 2N).
// Stage layout: [Ah 8KB][Al 8KB iff TERMS==2][B 8KB]  => STAGE=(TERMS+1)*8KB
// EPI 0: relu^2 -> fp16 hi into Cb. EPI 1: f32 copy to Cf.
// EPI 3: sigmoid * kv[slot] scattered to out[token] (fused combine).
// ---------------------------------------------------------------------------
template<int EPI, int TCH, int TERMS>
__global__ void __launch_bounds__(256, 2)
gemm_mma(const __half* __restrict__ Ag, const __half* __restrict__ Bg,
         float* __restrict__ Cf, __half* __restrict__ Cb,
         const float* __restrict__ KV, int N) {
    constexpr int K      = TCH * 32;
    constexpr int AROW_B = 2 * TERMS * K;
    constexpr int BROW_B = 2 * K;
    constexpr int STAGE  = (TERMS + 1) * 8192;
    constexpr int BOFF   = TERMS * 8192;

    extern __shared__ __align__(1024) char smem[];
    const uint32_t sb = smem_u32(smem);
    const int tid = threadIdx.x;
    const int lane = tid & 31, warp = tid >> 5;
    const int wm = warp & 3, wn = warp >> 2;
    const int e = blockIdx.z;
    const int bm = blockIdx.y * 128, bn = blockIdx.x * 128;

    const char* Ahi = (const char*)Ag + ((size_t)e * 2048 + bm) * AROW_B;
    const char* Alo = Ahi + 2 * K;
    const char* B   = (const char*)Bg + ((size_t)e * N + bn) * BROW_B;

    const int lr = tid >> 2, lc = tid & 3;
    const uint32_t sw0 = (uint32_t)(lr * 64 + ((lc ^ ((lr >> 1) & 3)) << 4));
    const uint32_t sw1 = (uint32_t)((lr + 64) * 64 + ((lc ^ (((lr + 64) >> 1) & 3)) << 4));
    const uint32_t cbL = (uint32_t)(lc * 16);

    auto load_stage = [&](int st, int kt) {
        const int colB = kt * 64;
        const uint32_t b = sb + st * STAGE;
        cp16(b + sw0, Ahi + (size_t)lr * AROW_B + colB + cbL);
        cp16(b + sw1, Ahi + (size_t)(lr + 64) * AROW_B + colB + cbL);
        if (TERMS == 2) {
            cp16(b + 8192 + sw0, Alo + (size_t)lr * AROW_B + colB + cbL);
            cp16(b + 8192 + sw1, Alo + (size_t)(lr + 64) * AROW_B + colB + cbL);
        }
        cp16(b + BOFF + sw0, B + (size_t)lr * BROW_B + colB + cbL);
        cp16(b + BOFF + sw1, B + (size_t)(lr + 64) * BROW_B + colB + cbL);
    };

    const int rowA0 = wm * 32 + (lane & 15);
    const uint32_t aOff = (uint32_t)(rowA0 * 64 +
                          (((lane >> 4) ^ ((rowA0 >> 1) & 3)) << 4));
    const int rowB0 = wn * 64 + (lane & 7) + ((lane >> 4) << 3);
    const uint32_t bOff = (uint32_t)(rowB0 * 64 +
                          ((((lane >> 3) & 1) ^ ((rowB0 >> 1) & 3)) << 4));

    float acc[2][8][4];
    #pragma unroll
    for (int i = 0; i < 2; ++i)
        #pragma unroll
        for (int j = 0; j < 8; ++j)
            #pragma unroll
            for (int k = 0; k < 4; ++k) acc[i][j][k] = 0.f;

    load_stage(0, 0); CP_COMMIT();
    load_stage(1, 1); CP_COMMIT();
    load_stage(2, 2); CP_COMMIT();

    for (int kt = 0; kt < TCH; ++kt) {
        CP_WAIT2();
        __syncthreads();
        if (kt + 3 < TCH) load_stage((kt + 3) & 3, kt + 3);
        CP_COMMIT();

        const uint32_t stb = sb + (kt & 3) * STAGE;
        #pragma unroll
        for (int ks = 0; ks < 2; ++ks) {
            const uint32_t kx = ks * 32;
            uint32_t ah[2][4], al[2][4];
            #pragma unroll
            for (int mi = 0; mi < 2; ++mi) {
                LDSM_X4(ah[mi], (stb + aOff + mi * 1024) ^ kx);
                if (TERMS == 2) LDSM_X4(al[mi], (stb + 8192 + aOff + mi * 1024) ^ kx);
            }
            uint32_t b[4][4];
            #pragma unroll
            for (int nf2 = 0; nf2 < 4; ++nf2)
                LDSM_X4(b[nf2], (stb + BOFF + bOff + nf2 * 1024) ^ kx);
            #pragma unroll
            for (int mi = 0; mi < 2; ++mi)
                #pragma unroll
                for (int nf2 = 0; nf2 < 4; ++nf2) {
                    mma_fp16(acc[mi][nf2 * 2 + 0], ah[mi], b[nf2][0], b[nf2][1]);
                    mma_fp16(acc[mi][nf2 * 2 + 1], ah[mi], b[nf2][2], b[nf2][3]);
                    if (TERMS == 2) {
                        mma_fp16(acc[mi][nf2 * 2 + 0], al[mi], b[nf2][0], b[nf2][1]);
                        mma_fp16(acc[mi][nf2 * 2 + 1], al[mi], b[nf2][2], b[nf2][3]);
                    }
                }
        }
    }

    // Epilogue
    #pragma unroll
    for (int mi = 0; mi < 2; ++mi) {
        #pragma unroll
        for (int nf = 0; nf < 8; ++nf) {
            const float* c = acc[mi][nf];
            const int col = bn + wn * 64 + nf * 8 + (lane & 3) * 2;
            const int row0 = bm + wm * 32 + mi * 16 + (lane >> 2);
            #pragma unroll
            for (int hh = 0; hh < 2; ++hh) {
                const int row = row0 + hh * 8;
                float v0 = c[hh * 2 + 0], v1 = c[hh * 2 + 1];
                if (EPI == 0) {
                    v0 = v0 > 0.f ? v0 * v0 : 0.f;
                    v1 = v1 > 0.f ? v1 * v1 : 0.f;
                    __half* p = Cb + ((size_t)e * 2048 + row) * (size_t)N + col;
                    *(__half2*)p = __halves2half2(__float2half(v0), __float2half(v1));
                } else if (EPI == 1) {
                    float* p = Cf + ((size_t)e * 2048 + row) * (size_t)N + col;
                    *(float2*)p = make_float2(v0, v1);
                } else {   // EPI == 3: fused sigmoid * kv -> out[token]
                    const int slot = e * 2048 + row;
                    const int tokidx = g_slot2tok[slot];
                    if (tokidx >= 0) {
                        float2 kv = *(const float2*)&KV[(size_t)slot * N + col];
                        v0 = kv.x / (1.f + __expf(-v0));
                        v1 = kv.y / (1.f + __expf(-v1));
                        *(float2*)&Cf[(size_t)tokidx * N + col] = make_float2(v0, v1);
                    }
                }
            }
        }
    }
}

// ---------------------------------------------------------------------------
// Zero-fill for dropped tokens; shift state
// ---------------------------------------------------------------------------
__global__ void zero_dropped_kernel(float* __restrict__ out) {
    const int s = blockIdx.x;
    if (g_tok2slot[s] != DROPPED) return;
    const int j = threadIdx.x * 4;
    *(float4*)&out[(size_t)s * Mm + j] = make_float4(0.f, 0.f, 0.f, 0.f);
}
__global__ void shift_kernel(const float* __restrict__ x, float* __restrict__ out) {
    const int b = blockIdx.x;
    const int j = threadIdx.x * 4;
    *(float4*)&out[(size_t)Ss * Mm + (size_t)b * Mm + j] =
        *(const float4*)&x[((size_t)b * Tt + (Tt - 1)) * Mm + j];
}

// ---------------------------------------------------------------------------
// Host
// ---------------------------------------------------------------------------
extern "C" void kernel_launch(void* const* d_in, const int* in_sizes, int n_in,
                              void* d_out, int out_size) {
    const float* x     = (const float*)d_in[0];
    const int*   tok   = (const int*)  d_in[1];
    const float* shift = (const float*)d_in[2];
    const float* maak  = (const float*)d_in[3];
    const float* maar  = (const float*)d_in[4];
    const float* Wk    = (const float*)d_in[5];
    const float* Wv    = (const float*)d_in[6];
    const float* Wr    = (const float*)d_in[7];
    float* out = (float*)d_out;

    void *dkh, *drh, *hh, *wkh, *wvh, *wrh, *kvp;
    cudaGetSymbolAddress(&dkh, g_dk_h);
    cudaGetSymbolAddress(&drh, g_dr_h);
    cudaGetSymbolAddress(&hh,  g_h_h);
    cudaGetSymbolAddress(&wkh, g_Wk_h);
    cudaGetSymbolAddress(&wvh, g_Wv_h);
    cudaGetSymbolAddress(&wrh, g_Wr_h);
    cudaGetSymbolAddress(&kvp, g_kv);

    constexpr int SM1 = 4 * 24576;   // TERMS=2: 4 stages x 24KB
    constexpr int SM2 = 4 * 16384;   // TERMS=1: 4 stages x 16KB
    cudaFuncSetAttribute((const void*)gemm_mma<0, 32, 2>,
                         cudaFuncAttributeMaxDynamicSharedMemorySize, SM1);
    cudaFuncSetAttribute((const void*)gemm_mma<1, 64, 1>,
                         cudaFuncAttributeMaxDynamicSharedMemorySize, SM2);
    cudaFuncSetAttribute((const void*)gemm_mma<3, 32, 1>,
                         cudaFuncAttributeMaxDynamicSharedMemorySize, SM2);

    route_kernel<<<1, 256>>>(tok);
    dispatch_kernel<<<ECAP, 256>>>(x, shift, maak, maar);
    wconv_fp16_kernel<<<dim3(64, 16, 8), dim3(32, 8)>>>(Wk, (__half*)wkh, 1024, 2048);
    wconv_fp16_kernel<<<dim3(32, 32, 8), dim3(32, 8)>>>(Wv, (__half*)wvh, 2048, 1024);
    wconv_fp16_kernel<<<dim3(32, 16, 8), dim3(32, 8)>>>(Wr, (__half*)wrh, 1024, 1024);

    // h = relu^2(dk @ Wk): 2-term, K=1024; writes fp16 hi only
    gemm_mma<0, 32, 2><<<dim3(16, 16, 8), 256, SM1>>>(
        (const __half*)dkh, (const __half*)wkh, nullptr, (__half*)hh, nullptr, 2048);
    // kv = h @ Wv: single-term fp16, K=2048
    gemm_mma<1, 64, 1><<<dim3(8, 16, 8), 256, SM2>>>(
        (const __half*)hh, (const __half*)wvh, (float*)kvp, nullptr, nullptr, 1024);
    // out[token] = sigmoid(dr @ Wr) * kv (fused combine): single-term, K=1024
    gemm_mma<3, 32, 1><<<dim3(8, 16, 8), 256, SM2>>>(
        (const __half*)drh, (const __half*)wrh, out, nullptr,
        (const float*)kvp, 1024);

    zero_dropped_kernel<<<Ss, 256>>>(out);
    if ((size_t)out_size >= (size_t)Ss * Mm + (size_t)Bb * Mm)
        shift_kernel<<<Bb, 256>>>(x, out);
}